// round 11
// baseline (speedup 1.0000x reference)
#include <cuda_runtime.h>
#include <cstdint>
#include <math.h>

// Problem constants
constexpr int B = 2;
constexpr int H = 16;
constexpr int N = 2048;
constexpr int A = 128;           // head dim
constexpr int W = 2048;          // model width
constexpr int HD = H * A;        // 2048
constexpr int Mdim = B * N;      // 4096
constexpr int Kdim = W;          // 2048

// Scratch (device globals — no allocation allowed)
__device__ float g_qr [Mdim * Kdim];     // tf32-rounded q
__device__ float g_Wqr[HD * W];
__device__ float g_Wkr[HD * W];
__device__ float g_Wvr[HD * W];
__device__ float g_Wor[W * HD];
__device__ float g_Q  [B * H * N * A];   // head-major (rope applied)
__device__ float g_K  [B * H * N * A];
__device__ float g_V  [B * H * N * A];
__device__ float g_AO [Mdim * HD];       // [b*n, h*a], rna-rounded by attention
__device__ float2 g_rope[N * 64];        // (sin, cos) per (n, pair)

// ---------------------------------------------------------------------------
// helpers
// ---------------------------------------------------------------------------
__device__ __forceinline__ float rna_tf32(float x) {
    uint32_t u;
    asm("cvt.rna.tf32.f32 %0, %1;" : "=r"(u) : "f"(x));
    return __uint_as_float(u);
}
__device__ __forceinline__ uint32_t rna_tf32_bits(float x) {
    uint32_t u;
    asm("cvt.rna.tf32.f32 %0, %1;" : "=r"(u) : "f"(x));
    return u;
}
__device__ __forceinline__ float ex2f(float x) {
    float y;
    asm("ex2.approx.ftz.f32 %0, %1;" : "=f"(y) : "f"(x));
    return y;
}
__device__ __forceinline__ uint32_t smem_u32(const void* p) {
    uint32_t a;
    asm("{ .reg .u64 t; cvta.to.shared.u64 t, %1; cvt.u32.u64 %0, t; }"
        : "=r"(a) : "l"(p));
    return a;
}
__device__ __forceinline__ void mma_tf32(float* c, const uint32_t* a,
                                         uint32_t b0, uint32_t b1) {
    asm volatile(
        "mma.sync.aligned.m16n8k8.row.col.f32.tf32.tf32.f32 "
        "{%0,%1,%2,%3}, {%4,%5,%6,%7}, {%8,%9}, {%0,%1,%2,%3};"
        : "+f"(c[0]), "+f"(c[1]), "+f"(c[2]), "+f"(c[3])
        : "r"(a[0]), "r"(a[1]), "r"(a[2]), "r"(a[3]), "r"(b0), "r"(b1));
}
__device__ __forceinline__ void ldsm_x4(uint32_t* r, uint32_t addr) {
    asm volatile("ldmatrix.sync.aligned.m8n8.x4.shared.b16 {%0,%1,%2,%3}, [%4];"
                 : "=r"(r[0]), "=r"(r[1]), "=r"(r[2]), "=r"(r[3]) : "r"(addr));
}
#define CP_ASYNC4(dst, src) \
    asm volatile("cp.async.ca.shared.global [%0], [%1], 4;" :: "r"(dst), "l"(src))
#define CP_ASYNC16(dst, src) \
    asm volatile("cp.async.cg.shared.global [%0], [%1], 16;" :: "r"(dst), "l"(src))
#define CP_COMMIT() asm volatile("cp.async.commit_group;" ::: "memory")
#define CP_WAIT(n)  asm volatile("cp.async.wait_group %0;" :: "n"(n) : "memory")
#define BAR_SYNC(id, cnt) \
    asm volatile("bar.sync %0, %1;" :: "r"(id), "r"(cnt) : "memory")

// ---------------------------------------------------------------------------
// rope sin/cos table: theta[n, i] = n * 10000^{-i/63}
// ---------------------------------------------------------------------------
__global__ void rope_table_kernel() {
    int idx = blockIdx.x * blockDim.x + threadIdx.x;   // [0, 2048*64)
    int i = idx & 63, n = idx >> 6;
    float freq = __powf(10000.0f, -(float)i * (1.0f / 63.0f));
    float s, c;
    sincosf((float)n * freq, &s, &c);
    g_rope[idx] = make_float2(s, c);
}

// ---------------------------------------------------------------------------
// Fused rna-rounding pre-pass over q + 4 weights (single DRAM-bound launch).
// ---------------------------------------------------------------------------
constexpr int NQ4 = Mdim * Kdim / 4;   // 2,097,152
constexpr int NW4 = HD * W / 4;        // 1,048,576 = 2^20

__global__ void round_all_kernel(const float4* __restrict__ q,
                                 const float4* __restrict__ wq,
                                 const float4* __restrict__ wk,
                                 const float4* __restrict__ wv,
                                 const float4* __restrict__ wo,
                                 float4* __restrict__ qr,
                                 float4* __restrict__ wqr,
                                 float4* __restrict__ wkr,
                                 float4* __restrict__ wvr,
                                 float4* __restrict__ wor) {
    int i = blockIdx.x * blockDim.x + threadIdx.x;
    const float4* src;
    float4* dst;
    int off;
    if (i < NQ4) {
        src = q; dst = qr; off = i;
    } else {
        int j = i - NQ4;
        int w = j >> 20;
        off = j & (NW4 - 1);
        src = (w == 0) ? wq : (w == 1) ? wk : (w == 2) ? wv : wo;
        dst = (w == 0) ? wqr : (w == 1) ? wkr : (w == 2) ? wvr : wor;
    }
    float4 v = src[off];
    v.x = rna_tf32(v.x); v.y = rna_tf32(v.y);
    v.z = rna_tf32(v.z); v.w = rna_tf32(v.w);
    dst[off] = v;
}

// ---------------------------------------------------------------------------
// tf32 mma.sync GEMM (unchanged): 128x128 CTA, BK=32, 4 warps of 64x64,
// 3-stage cp.async pipeline, XOR-swizzled row-major smem, ldmatrix.x4.
// Optional fused RoPE in the epilogue (Q/K projections).
// ---------------------------------------------------------------------------
constexpr int TILE_B     = 128 * 32 * 4;          // 16384 per operand
constexpr int STAGE_B    = 2 * TILE_B;            // 32768
constexpr int GEMM_SMEM  = 3 * STAGE_B;           // 98304

template <int SCATTER_C>
__device__ __forceinline__ void gemm_body(const float* __restrict__ Ag,
                                          const float* __restrict__ Bg,
                                          float* __restrict__ Cg,
                                          bool doRope) {
    extern __shared__ float gs[];
    const uint32_t sbase = smem_u32(gs);
    const int tid  = threadIdx.x;
    const int lane = tid & 31;
    const int wid  = tid >> 5;      // 0..3
    const int wm   = wid & 1;       // 64 rows each
    const int wn   = wid >> 1;      // 64 cols each
    const int m0   = blockIdx.y * 128;
    const int n0   = blockIdx.x * 128;

    float c[4][8][4];
#pragma unroll
    for (int mi = 0; mi < 4; mi++)
#pragma unroll
        for (int ni = 0; ni < 8; ni++)
#pragma unroll
            for (int j = 0; j < 4; j++) c[mi][ni][j] = 0.f;

    const int srow0 = tid >> 3;     // 0..15
    const int sc16  = tid & 7;
    auto stage = [&](int kt, int slot) {
        const uint32_t base = sbase + slot * STAGE_B;
        const float* Asrc = Ag + (size_t)(m0 + srow0) * Kdim + kt * 32 + sc16 * 4;
        const float* Bsrc = Bg + (size_t)(n0 + srow0) * Kdim + kt * 32 + sc16 * 4;
#pragma unroll
        for (int i = 0; i < 8; i++) {
            int row = srow0 + i * 16;
            uint32_t off = (uint32_t)row * 128 + ((sc16 ^ (row & 7)) << 4);
            CP_ASYNC16(base + off,          Asrc + (size_t)i * 16 * Kdim);
            CP_ASYNC16(base + TILE_B + off, Bsrc + (size_t)i * 16 * Kdim);
        }
    };

    const int a_row = wm * 64 + (lane & 15);
    const int a_hi  = lane >> 4;
    const int b_row = wn * 64 + (lane & 7) + ((lane >> 4) << 3);
    const int b_hi  = (lane >> 3) & 1;

    stage(0, 0); CP_COMMIT();
    stage(1, 1); CP_COMMIT();

    constexpr int NKT = Kdim / 32;
    int slot = 0;
    for (int kt = 0; kt < NKT; kt++) {
        CP_WAIT(1);
        __syncthreads();
        if (kt + 2 < NKT) {
            int ns = slot + 2; if (ns >= 3) ns -= 3;
            stage(kt + 2, ns);
        }
        CP_COMMIT();

        const uint32_t abase = sbase + slot * STAGE_B;
        const uint32_t bbase = abase + TILE_B;
#pragma unroll
        for (int ks = 0; ks < 4; ks++) {
            uint32_t af[4][4];
#pragma unroll
            for (int mi = 0; mi < 4; mi++) {
                int row = a_row + mi * 16;
                uint32_t addr = abase + (uint32_t)row * 128
                              + (((ks * 2 + a_hi) ^ (row & 7)) << 4);
                ldsm_x4(af[mi], addr);
            }
#pragma unroll
            for (int nip = 0; nip < 4; nip++) {
                int row = b_row + nip * 16;
                uint32_t addr = bbase + (uint32_t)row * 128
                              + (((ks * 2 + b_hi) ^ (row & 7)) << 4);
                uint32_t bf[4];
                ldsm_x4(bf, addr);
#pragma unroll
                for (int mi = 0; mi < 4; mi++) {
                    mma_tf32(c[mi][2 * nip],     af[mi], bf[0], bf[1]);
                    mma_tf32(c[mi][2 * nip + 1], af[mi], bf[2], bf[3]);
                }
            }
        }
        slot++; if (slot >= 3) slot = 0;
    }

    const int gid = lane >> 2, tig = lane & 3;
#pragma unroll
    for (int mi = 0; mi < 4; mi++) {
#pragma unroll
        for (int ni = 0; ni < 8; ni++) {
            int n = n0 + wn * 64 + ni * 8 + tig * 2;
#pragma unroll
            for (int half = 0; half < 2; half++) {
                int m = m0 + wm * 64 + mi * 16 + gid + half * 8;
                float2 v = make_float2(c[mi][ni][half * 2], c[mi][ni][half * 2 + 1]);
                if (doRope) {
                    int pi   = (n & 127) >> 1;
                    int npos = m & 2047;
                    float2 sc = g_rope[(npos << 6) + pi];
                    float ev = v.x * sc.y - v.y * sc.x;
                    float ov = v.y * sc.y + v.x * sc.x;
                    v = make_float2(ev, ov);
                }
                size_t dst;
                if (SCATTER_C) {
                    int b2 = m >> 11, np = m & 2047, h2 = n >> 7, a0 = n & 127;
                    dst = ((((size_t)b2 * H + h2) * N) + np) * A + a0;
                } else {
                    dst = (size_t)m * 2048 + n;
                }
                *(float2*)(Cg + dst) = v;
            }
        }
    }
}

__global__ __launch_bounds__(128, 2)
void qkv_gemm(const float* __restrict__ q,
              const float* __restrict__ Wq, const float* __restrict__ Wk,
              const float* __restrict__ Wv,
              float* __restrict__ Qp, float* __restrict__ Kp,
              float* __restrict__ Vp) {
    const int z = blockIdx.z;
    const float* Bg = (z == 0) ? Wq : (z == 1) ? Wk : Wv;
    float*       Cg = (z == 0) ? Qp : (z == 1) ? Kp : Vp;
    gemm_body<1>(q, Bg, Cg, z < 2);
}

__global__ __launch_bounds__(128, 2)
void out_gemm(const float* __restrict__ Ag, const float* __restrict__ Bg,
              float* __restrict__ Cg) {
    gemm_body<0>(Ag, Bg, Cg, false);
}

// ---------------------------------------------------------------------------
// Tensor-core causal flash attention v6 — d-split warp pairs.
// CTA: 32 queries, 128 threads (4 warps). Warp pairs (0,2)/(1,3) share 16
// query rows; each warp owns half of d (64). S computed as partial sums over
// the warp's 8 kd-frags, exchanged via smem + named barrier, summed; softmax
// duplicated in the pair; PV against the warp's V d-half only.
// Permuted-K layout retained (S C-frag == P A-frag up to register rename).
// smem 72KB, target 3 CTAs/SM (12 warps).
// ---------------------------------------------------------------------------
constexpr int AQT = 32;
constexpr int AKT = 32;
constexpr int K_TILE_B  = AKT * 128 * 4;          // 16384 B
constexpr int STAGE_F   = AKT * 128 * 2;          // 8192 floats (K + V)
constexpr int ATTN_SMEM = 2 * STAGE_F * 4 + 4 * 2048;   // 65536 + 8192 = 73728

__global__ __launch_bounds__(128, 3)
void attn_mma_kernel(const float* __restrict__ Q, const float* __restrict__ K,
                     const float* __restrict__ V, float* __restrict__ O) {
    extern __shared__ float smx[];
    const uint32_t sbase = smem_u32(smx);

    const int tid  = threadIdx.x;
    const int lane = tid & 31;
    const int wid  = tid >> 5;          // 0..3
    const int qh   = wid & 1;           // query half (16 rows)
    const int dh   = wid >> 1;          // d half (64 dims)
    const int gid  = lane >> 2, tig = lane & 3;
    const int bh   = blockIdx.y;
    const int qt   = gridDim.x - 1 - blockIdx.x;   // heavy tiles first
    const int q0   = qt * AQT;

    const float* Qb = Q + (size_t)bh * N * A;
    const float* Kb = K + (size_t)bh * N * A;
    const float* Vb = V + (size_t)bh * N * A;

    // ---- stage Q (32 rows x 512B) row-major swizzled into stage-0 alias ----
    {
        const int c16 = tid & 31;
        const int r0  = tid >> 5;       // 0..3
#pragma unroll
        for (int i = 0; i < 8; i++) {
            int row = r0 + i * 4;       // 0..31
            uint32_t off = (uint32_t)row * 512 + ((c16 ^ (row & 7)) << 4);
            CP_ASYNC16(sbase + off, Qb + (size_t)(q0 + row) * A + c16 * 4);
        }
        CP_COMMIT();
        CP_WAIT(0);
        __syncthreads();
    }

    // ---- Q A-frags (own query half, own d half); fold scale*log2e ----
    const float scl = 0.08838834764831845f * 1.4426950408889634f;
    uint32_t qf[8][4];
    {
        const int a_row = qh * 16 + (lane & 15);
        const int a_hi  = lane >> 4;
#pragma unroll
        for (int k8 = 0; k8 < 8; k8++) {
            int kd = dh * 8 + k8;
            uint32_t addr = sbase + (uint32_t)a_row * 512
                          + (((kd * 2 + a_hi) ^ (a_row & 7)) << 4);
            ldsm_x4(qf[k8], addr);
#pragma unroll
            for (int j = 0; j < 4; j++)
                qf[k8][j] = rna_tf32_bits(__uint_as_float(qf[k8][j]) * scl);
        }
    }
    __syncthreads();   // Q smem now reusable as KV stage 0

    // ---- KV staging (K rows permuted within 8-groups) ----
    const int s_c16 = tid & 31;
    const int s_r0  = tid >> 5;
    const int v_d7  = (tid & 7) * 4;
    const int v_pos = ((tid >> 3) & 1) * 2;
    const int v_chk = tid >> 4;
    auto stage = [&](int kt, int slot) {
        const uint32_t kb = sbase + slot * (STAGE_F * 4);
        const uint32_t vb = kb + K_TILE_B;
        const float* Kg = Kb + (size_t)(kt * AKT) * A;
        const float* Vg = Vb + (size_t)(kt * AKT) * A + tid;
#pragma unroll
        for (int i = 0; i < 8; i++) {
            int row  = s_r0 + i * 4;   // key index 0..31
            int prow = (row & ~7) | ((row & 3) << 1) | ((row >> 2) & 1);
            uint32_t off = (uint32_t)prow * 512 + ((s_c16 ^ (prow & 7)) << 4);
            CP_ASYNC16(kb + off, Kg + (size_t)row * A + s_c16 * 4);
        }
#pragma unroll
        for (int key = 0; key < 32; key++) {
            int kf    = key >> 3;
            int lanev = v_d7 + (key & 3);
            int chunk = v_chk ^ (lanev & 7);
            int pos   = v_pos + ((key >> 2) & 1);
            uint32_t va = vb + ((((kf * 32 + lanev) * 32) + chunk * 4 + pos) << 2);
            CP_ASYNC4(va, Vg + (size_t)key * A);
        }
    };

    const int nkt = qt + 1;   // all warps process every tile

    // S-exchange buffers: 4 x 2KB after the stages
    float4* exw = (float4*)(smx + 2 * STAGE_F) + wid * 128;
    float4* exp_ = (float4*)(smx + 2 * STAGE_F) + (wid ^ 2) * 128;
    const int bar_id = 1 + qh;

    float o[8][4];
#pragma unroll
    for (int nf = 0; nf < 8; nf++)
#pragma unroll
        for (int j = 0; j < 4; j++) o[nf][j] = 0.f;
    float m0 = -1e30f, m1 = -1e30f, l0 = 0.f, l1 = 0.f;

    const int row0 = q0 + qh * 16 + gid;
    const int row1 = row0 + 8;
    const int b_row = (lane & 7) + ((lane >> 4) << 3);   // 0..15
    const int b_hi  = (lane >> 3) & 1;

    stage(0, 0); CP_COMMIT();
    stage(1, 1); CP_COMMIT();

    for (int kt = 0; kt < nkt; kt++) {
        const int buf = kt & 1;
        if (kt < nkt - 1) { CP_WAIT(1); } else { CP_WAIT(0); }
        __syncthreads();

        const uint32_t kbase = sbase + buf * (STAGE_F * 4);
        const float*   vbuf  = smx + buf * STAGE_F + AKT * 128;

        // ---- partial S over own d half (8 kd frags) ----
        float s[4][4];
#pragma unroll
        for (int nk = 0; nk < 4; nk++)
#pragma unroll
            for (int j = 0; j < 4; j++) s[nk][j] = 0.f;

#pragma unroll
        for (int k8 = 0; k8 < 8; k8++) {
            int kd = dh * 8 + k8;
            uint32_t col = ((kd * 2 + b_hi) ^ (b_row & 7)) << 4;
            uint32_t kfA[4], kfB[4];
            ldsm_x4(kfA, kbase + (uint32_t)b_row * 512 + col);
            ldsm_x4(kfB, kbase + (uint32_t)(b_row + 16) * 512 + col);
            mma_tf32(s[0], qf[k8], kfA[0], kfA[1]);
            mma_tf32(s[1], qf[k8], kfA[2], kfA[3]);
            mma_tf32(s[2], qf[k8], kfB[0], kfB[1]);
            mma_tf32(s[3], qf[k8], kfB[2], kfB[3]);
        }

        // ---- pair exchange: write own partial, add partner's ----
#pragma unroll
        for (int nk = 0; nk < 4; nk++)
            exw[nk * 32 + lane] = make_float4(s[nk][0], s[nk][1], s[nk][2], s[nk][3]);
        BAR_SYNC(bar_id, 64);
#pragma unroll
        for (int nk = 0; nk < 4; nk++) {
            float4 p = exp_[nk * 32 + lane];
            s[nk][0] += p.x; s[nk][1] += p.y;
            s[nk][2] += p.z; s[nk][3] += p.w;
        }

        // ---- causal mask (diagonal tile only; permuted columns) ----
        if (kt == nkt - 1) {
            int colb = kt * AKT + tig;
#pragma unroll
            for (int nk = 0; nk < 4; nk++) {
                int c0 = colb + nk * 8;
                if (c0     > row0) s[nk][0] = -1e30f;
                if (c0 + 4 > row0) s[nk][1] = -1e30f;
                if (c0     > row1) s[nk][2] = -1e30f;
                if (c0 + 4 > row1) s[nk][3] = -1e30f;
            }
        }

        // ---- online softmax (log2 domain; duplicated in the pair) ----
        float mx0 = -1e30f, mx1 = -1e30f;
#pragma unroll
        for (int nk = 0; nk < 4; nk++) {
            mx0 = fmaxf(mx0, fmaxf(s[nk][0], s[nk][1]));
            mx1 = fmaxf(mx1, fmaxf(s[nk][2], s[nk][3]));
        }
        mx0 = fmaxf(mx0, __shfl_xor_sync(0xffffffffu, mx0, 1));
        mx0 = fmaxf(mx0, __shfl_xor_sync(0xffffffffu, mx0, 2));
        mx1 = fmaxf(mx1, __shfl_xor_sync(0xffffffffu, mx1, 1));
        mx1 = fmaxf(mx1, __shfl_xor_sync(0xffffffffu, mx1, 2));
        float mn0 = fmaxf(m0, mx0), mn1 = fmaxf(m1, mx1);
        float cor0 = ex2f(m0 - mn0), cor1 = ex2f(m1 - mn1);
        m0 = mn0; m1 = mn1;

        float rs0 = 0.f, rs1 = 0.f;
#pragma unroll
        for (int nk = 0; nk < 4; nk++) {
            s[nk][0] = ex2f(s[nk][0] - mn0);
            s[nk][1] = ex2f(s[nk][1] - mn0);
            s[nk][2] = ex2f(s[nk][2] - mn1);
            s[nk][3] = ex2f(s[nk][3] - mn1);
            rs0 += s[nk][0] + s[nk][1];
            rs1 += s[nk][2] + s[nk][3];
        }
        rs0 += __shfl_xor_sync(0xffffffffu, rs0, 1);
        rs0 += __shfl_xor_sync(0xffffffffu, rs0, 2);
        rs1 += __shfl_xor_sync(0xffffffffu, rs1, 1);
        rs1 += __shfl_xor_sync(0xffffffffu, rs1, 2);
        l0 = l0 * cor0 + rs0;
        l1 = l1 * cor1 + rs1;

#pragma unroll
        for (int nf = 0; nf < 8; nf++) {
            o[nf][0] *= cor0; o[nf][1] *= cor0;
            o[nf][2] *= cor1; o[nf][3] *= cor1;
        }

        // ---- P A-frags = register rename of S C-frags ----
        uint32_t aP[4][4];
#pragma unroll
        for (int kf = 0; kf < 4; kf++) {
            aP[kf][0] = rna_tf32_bits(s[kf][0]);
            aP[kf][1] = rna_tf32_bits(s[kf][2]);
            aP[kf][2] = rna_tf32_bits(s[kf][1]);
            aP[kf][3] = rna_tf32_bits(s[kf][3]);
        }

        // ---- O += P V (own d half: 4 of 8 d-chunks) ----
        const float* vrow = vbuf + (uint32_t)lane * 32;
        const int ln7 = (lane & 7);
#pragma unroll
        for (int kf = 0; kf < 4; kf++) {
            const float* vk = vrow + kf * 32 * 32;
#pragma unroll
            for (int j2l = 0; j2l < 4; j2l++) {
                int j2 = dh * 4 + j2l;
                float4 vv = *(const float4*)(vk + ((j2 ^ ln7) << 2));
                mma_tf32(o[2 * j2l],     aP[kf], __float_as_uint(vv.x),
                                                 __float_as_uint(vv.y));
                mma_tf32(o[2 * j2l + 1], aP[kf], __float_as_uint(vv.z),
                                                 __float_as_uint(vv.w));
            }
        }

        __syncthreads();
        if (kt + 2 < nkt) { stage(kt + 2, buf); CP_COMMIT(); }
    }

    // ---- write output: [b*n, h*a] (own d half), rna for Wo GEMM ----
    const float il0 = 1.f / l0, il1 = 1.f / l1;
    const int b2 = bh >> 4, h2 = bh & 15;
    float* o0 = O + (size_t)(b2 * N + row0) * HD + h2 * A + dh * 64;
    float* o1 = O + (size_t)(b2 * N + row1) * HD + h2 * A + dh * 64;
#pragma unroll
    for (int nf = 0; nf < 8; nf++) {
        int col = nf * 8 + 2 * tig;
        *(float2*)(o0 + col) = make_float2(rna_tf32(o[nf][0] * il0),
                                           rna_tf32(o[nf][1] * il0));
        *(float2*)(o1 + col) = make_float2(rna_tf32(o[nf][2] * il1),
                                           rna_tf32(o[nf][3] * il1));
    }
}

// ---------------------------------------------------------------------------
extern "C" void kernel_launch(void* const* d_in, const int* in_sizes, int n_in,
                              void* d_out, int out_size) {
    const float* q  = (const float*)d_in[0];
    const float* Wq = (const float*)d_in[1];
    const float* Wk = (const float*)d_in[2];
    const float* Wv = (const float*)d_in[3];
    const float* Wo = (const float*)d_in[4];
    float* out = (float*)d_out;

    float *qr, *Wqr, *Wkr, *Wvr, *Wor, *Qp, *Kp, *Vp, *AOp;
    cudaGetSymbolAddress((void**)&qr,  g_qr);
    cudaGetSymbolAddress((void**)&Wqr, g_Wqr);
    cudaGetSymbolAddress((void**)&Wkr, g_Wkr);
    cudaGetSymbolAddress((void**)&Wvr, g_Wvr);
    cudaGetSymbolAddress((void**)&Wor, g_Wor);
    cudaGetSymbolAddress((void**)&Qp,  g_Q);
    cudaGetSymbolAddress((void**)&Kp,  g_K);
    cudaGetSymbolAddress((void**)&Vp,  g_V);
    cudaGetSymbolAddress((void**)&AOp, g_AO);

    cudaFuncSetAttribute(qkv_gemm, cudaFuncAttributeMaxDynamicSharedMemorySize,
                         GEMM_SMEM);
    cudaFuncSetAttribute(out_gemm, cudaFuncAttributeMaxDynamicSharedMemorySize,
                         GEMM_SMEM);
    cudaFuncSetAttribute(attn_mma_kernel,
                         cudaFuncAttributeMaxDynamicSharedMemorySize, ATTN_SMEM);

    // rope sin/cos table + fused rna pre-pass (q + 4 weights)
    rope_table_kernel<<<(N * 64) / 256, 256>>>();
    {
        int total = NQ4 + 4 * NW4;   // 6,291,456
        round_all_kernel<<<total / 256, 256>>>(
            (const float4*)q, (const float4*)Wq, (const float4*)Wk,
            (const float4*)Wv, (const float4*)Wo,
            (float4*)qr, (float4*)Wqr, (float4*)Wkr, (float4*)Wvr, (float4*)Wor);
    }

    // fused QKV projections (rope applied in epilogue for Q/K)
    qkv_gemm<<<dim3(16, 32, 3), 128, GEMM_SMEM>>>(qr, Wqr, Wkr, Wvr, Qp, Kp, Vp);

    // tensor-core causal flash attention (32q CTAs, d-split warp pairs)
    attn_mma_kernel<<<dim3(N / AQT, B * H), 128, ATTN_SMEM>>>(Qp, Kp, Vp, AOp);

    // output projection
    out_gemm<<<dim3(16, 32), 128, GEMM_SMEM>>>(AOp, Wor, out);
}

// round 12
// speedup vs baseline: 1.2127x; 1.2127x over previous
#include <cuda_runtime.h>
#include <cstdint>
#include <math.h>

// Problem constants
constexpr int B = 2;
constexpr int H = 16;
constexpr int N = 2048;
constexpr int A = 128;           // head dim
constexpr int W = 2048;          // model width
constexpr int HD = H * A;        // 2048
constexpr int Mdim = B * N;      // 4096
constexpr int Kdim = W;          // 2048

// Scratch (device globals — no allocation allowed)
__device__ float g_qr [Mdim * Kdim];     // tf32-rounded q
__device__ float g_Wqr[HD * W];
__device__ float g_Wkr[HD * W];
__device__ float g_Wvr[HD * W];
__device__ float g_Wor[W * HD];
__device__ float g_Q  [B * H * N * A];   // head-major (rope applied)
__device__ float g_K  [B * H * N * A];   // head-major (rope applied)
__device__ float g_VT [B * H * A * N];   // TRANSPOSED: [b][h][d][n]
__device__ float g_AO [Mdim * HD];       // [b*n, h*a], rna-rounded by attention
__device__ float2 g_rope[N * 64];        // (sin, cos) per (n, pair)

// ---------------------------------------------------------------------------
// helpers
// ---------------------------------------------------------------------------
__device__ __forceinline__ float rna_tf32(float x) {
    uint32_t u;
    asm("cvt.rna.tf32.f32 %0, %1;" : "=r"(u) : "f"(x));
    return __uint_as_float(u);
}
__device__ __forceinline__ uint32_t rna_tf32_bits(float x) {
    uint32_t u;
    asm("cvt.rna.tf32.f32 %0, %1;" : "=r"(u) : "f"(x));
    return u;
}
__device__ __forceinline__ float ex2f(float x) {
    float y;
    asm("ex2.approx.ftz.f32 %0, %1;" : "=f"(y) : "f"(x));
    return y;
}
__device__ __forceinline__ uint32_t smem_u32(const void* p) {
    uint32_t a;
    asm("{ .reg .u64 t; cvta.to.shared.u64 t, %1; cvt.u32.u64 %0, t; }"
        : "=r"(a) : "l"(p));
    return a;
}
__device__ __forceinline__ void mma_tf32(float* c, const uint32_t* a,
                                         uint32_t b0, uint32_t b1) {
    asm volatile(
        "mma.sync.aligned.m16n8k8.row.col.f32.tf32.tf32.f32 "
        "{%0,%1,%2,%3}, {%4,%5,%6,%7}, {%8,%9}, {%0,%1,%2,%3};"
        : "+f"(c[0]), "+f"(c[1]), "+f"(c[2]), "+f"(c[3])
        : "r"(a[0]), "r"(a[1]), "r"(a[2]), "r"(a[3]), "r"(b0), "r"(b1));
}
__device__ __forceinline__ void ldsm_x4(uint32_t* r, uint32_t addr) {
    asm volatile("ldmatrix.sync.aligned.m8n8.x4.shared.b16 {%0,%1,%2,%3}, [%4];"
                 : "=r"(r[0]), "=r"(r[1]), "=r"(r[2]), "=r"(r[3]) : "r"(addr));
}
#define CP_ASYNC16(dst, src) \
    asm volatile("cp.async.cg.shared.global [%0], [%1], 16;" :: "r"(dst), "l"(src))
#define CP_COMMIT() asm volatile("cp.async.commit_group;" ::: "memory")
#define CP_WAIT(n)  asm volatile("cp.async.wait_group %0;" :: "n"(n) : "memory")

// ---------------------------------------------------------------------------
// rope sin/cos table: theta[n, i] = n * 10000^{-i/63}
// ---------------------------------------------------------------------------
__global__ void rope_table_kernel() {
    int idx = blockIdx.x * blockDim.x + threadIdx.x;   // [0, 2048*64)
    int i = idx & 63, n = idx >> 6;
    float freq = __powf(10000.0f, -(float)i * (1.0f / 63.0f));
    float s, c;
    sincosf((float)n * freq, &s, &c);
    g_rope[idx] = make_float2(s, c);
}

// ---------------------------------------------------------------------------
// Fused rna-rounding pre-pass over q + 4 weights (single DRAM-bound launch).
// ---------------------------------------------------------------------------
constexpr int NQ4 = Mdim * Kdim / 4;   // 2,097,152
constexpr int NW4 = HD * W / 4;        // 1,048,576 = 2^20

__global__ void round_all_kernel(const float4* __restrict__ q,
                                 const float4* __restrict__ wq,
                                 const float4* __restrict__ wk,
                                 const float4* __restrict__ wv,
                                 const float4* __restrict__ wo,
                                 float4* __restrict__ qr,
                                 float4* __restrict__ wqr,
                                 float4* __restrict__ wkr,
                                 float4* __restrict__ wvr,
                                 float4* __restrict__ wor) {
    int i = blockIdx.x * blockDim.x + threadIdx.x;
    const float4* src;
    float4* dst;
    int off;
    if (i < NQ4) {
        src = q; dst = qr; off = i;
    } else {
        int j = i - NQ4;
        int w = j >> 20;
        off = j & (NW4 - 1);
        src = (w == 0) ? wq : (w == 1) ? wk : (w == 2) ? wv : wo;
        dst = (w == 0) ? wqr : (w == 1) ? wkr : (w == 2) ? wvr : wor;
    }
    float4 v = src[off];
    v.x = rna_tf32(v.x); v.y = rna_tf32(v.y);
    v.z = rna_tf32(v.z); v.w = rna_tf32(v.w);
    dst[off] = v;
}

// ---------------------------------------------------------------------------
// tf32 mma.sync GEMM: 128x128 CTA, BK=32, 4 warps of 64x64, 3-stage cp.async
// pipeline, XOR-swizzled row-major smem, ldmatrix.x4.
// Epilogue options: rope fusion (Q/K), head-major scatter, V transpose.
// ---------------------------------------------------------------------------
constexpr int TILE_B     = 128 * 32 * 4;          // 16384 per operand
constexpr int STAGE_B    = 2 * TILE_B;            // 32768
constexpr int GEMM_SMEM  = 3 * STAGE_B;           // 98304

template <int SCATTER_C>
__device__ __forceinline__ void gemm_body(const float* __restrict__ Ag,
                                          const float* __restrict__ Bg,
                                          float* __restrict__ Cg,
                                          bool doRope, bool transV) {
    extern __shared__ float gs[];
    const uint32_t sbase = smem_u32(gs);
    const int tid  = threadIdx.x;
    const int lane = tid & 31;
    const int wid  = tid >> 5;      // 0..3
    const int wm   = wid & 1;       // 64 rows each
    const int wn   = wid >> 1;      // 64 cols each
    const int m0   = blockIdx.y * 128;
    const int n0   = blockIdx.x * 128;

    float c[4][8][4];
#pragma unroll
    for (int mi = 0; mi < 4; mi++)
#pragma unroll
        for (int ni = 0; ni < 8; ni++)
#pragma unroll
            for (int j = 0; j < 4; j++) c[mi][ni][j] = 0.f;

    const int srow0 = tid >> 3;     // 0..15
    const int sc16  = tid & 7;
    auto stage = [&](int kt, int slot) {
        const uint32_t base = sbase + slot * STAGE_B;
        const float* Asrc = Ag + (size_t)(m0 + srow0) * Kdim + kt * 32 + sc16 * 4;
        const float* Bsrc = Bg + (size_t)(n0 + srow0) * Kdim + kt * 32 + sc16 * 4;
#pragma unroll
        for (int i = 0; i < 8; i++) {
            int row = srow0 + i * 16;
            uint32_t off = (uint32_t)row * 128 + ((sc16 ^ (row & 7)) << 4);
            CP_ASYNC16(base + off,          Asrc + (size_t)i * 16 * Kdim);
            CP_ASYNC16(base + TILE_B + off, Bsrc + (size_t)i * 16 * Kdim);
        }
    };

    const int a_row = wm * 64 + (lane & 15);
    const int a_hi  = lane >> 4;
    const int b_row = wn * 64 + (lane & 7) + ((lane >> 4) << 3);
    const int b_hi  = (lane >> 3) & 1;

    stage(0, 0); CP_COMMIT();
    stage(1, 1); CP_COMMIT();

    constexpr int NKT = Kdim / 32;
    int slot = 0;
    for (int kt = 0; kt < NKT; kt++) {
        CP_WAIT(1);
        __syncthreads();
        if (kt + 2 < NKT) {
            int ns = slot + 2; if (ns >= 3) ns -= 3;
            stage(kt + 2, ns);
        }
        CP_COMMIT();

        const uint32_t abase = sbase + slot * STAGE_B;
        const uint32_t bbase = abase + TILE_B;
#pragma unroll
        for (int ks = 0; ks < 4; ks++) {
            uint32_t af[4][4];
#pragma unroll
            for (int mi = 0; mi < 4; mi++) {
                int row = a_row + mi * 16;
                uint32_t addr = abase + (uint32_t)row * 128
                              + (((ks * 2 + a_hi) ^ (row & 7)) << 4);
                ldsm_x4(af[mi], addr);
            }
#pragma unroll
            for (int nip = 0; nip < 4; nip++) {
                int row = b_row + nip * 16;
                uint32_t addr = bbase + (uint32_t)row * 128
                              + (((ks * 2 + b_hi) ^ (row & 7)) << 4);
                uint32_t bf[4];
                ldsm_x4(bf, addr);
#pragma unroll
                for (int mi = 0; mi < 4; mi++) {
                    mma_tf32(c[mi][2 * nip],     af[mi], bf[0], bf[1]);
                    mma_tf32(c[mi][2 * nip + 1], af[mi], bf[2], bf[3]);
                }
            }
        }
        slot++; if (slot >= 3) slot = 0;
    }

    const int gid = lane >> 2, tig = lane & 3;
#pragma unroll
    for (int mi = 0; mi < 4; mi++) {
#pragma unroll
        for (int ni = 0; ni < 8; ni++) {
            int n = n0 + wn * 64 + ni * 8 + tig * 2;
#pragma unroll
            for (int half = 0; half < 2; half++) {
                int m = m0 + wm * 64 + mi * 16 + gid + half * 8;
                float2 v = make_float2(c[mi][ni][half * 2], c[mi][ni][half * 2 + 1]);
                if (doRope) {
                    int pi   = (n & 127) >> 1;
                    int npos = m & 2047;
                    float2 sc = g_rope[(npos << 6) + pi];
                    float ev = v.x * sc.y - v.y * sc.x;
                    float ov = v.y * sc.y + v.x * sc.x;
                    v = make_float2(ev, ov);
                }
                if (SCATTER_C) {
                    int b2 = m >> 11, np = m & 2047, h2 = n >> 7, a0 = n & 127;
                    if (transV) {
                        float* p = Cg + (((size_t)b2 * H + h2) * A + a0) * N + np;
                        p[0] = v.x;
                        p[N] = v.y;
                    } else {
                        *(float2*)(Cg + ((((size_t)b2 * H + h2) * N) + np) * A + a0) = v;
                    }
                } else {
                    *(float2*)(Cg + (size_t)m * 2048 + n) = v;
                }
            }
        }
    }
}

__global__ __launch_bounds__(128, 2)
void qkv_gemm(const float* __restrict__ q,
              const float* __restrict__ Wq, const float* __restrict__ Wk,
              const float* __restrict__ Wv,
              float* __restrict__ Qp, float* __restrict__ Kp,
              float* __restrict__ VTp) {
    const int z = blockIdx.z;
    const float* Bg = (z == 0) ? Wq : (z == 1) ? Wk : Wv;
    float*       Cg = (z == 0) ? Qp : (z == 1) ? Kp : VTp;
    gemm_body<1>(q, Bg, Cg, z < 2, z == 2);
}

__global__ __launch_bounds__(128, 2)
void out_gemm(const float* __restrict__ Ag, const float* __restrict__ Bg,
              float* __restrict__ Cg) {
    gemm_body<0>(Ag, Bg, Cg, false, false);
}

// ---------------------------------------------------------------------------
// Tensor-core causal flash attention v7 (v5 + Vt-ldmatrix + 3-stage pipe).
// CTA: 64 queries, 128 threads (4 warps x 16 q rows), 32-key tiles.
// K: row-major XOR-swizzled (permuted key rows) + ldmatrix.
// V: TRANSPOSED global [b][h][d][n] -> d-major smem (16B cp.async) + ldmatrix.
// 3-stage pipeline, ONE syncthreads per tile, staging overlapped with compute.
// S C-frag == P A-frag (register rename) via the permuted-K layout.
// ---------------------------------------------------------------------------
constexpr int AQT = 64;
constexpr int AKT = 32;
constexpr int K_TILE_B   = AKT * 128 * 4;          // 16384 B (32 rows x 512B)
constexpr int V_TILE_B   = 128 * AKT * 4;          // 16384 B (128 rows x 128B)
constexpr int ASTAGE_B   = K_TILE_B + V_TILE_B;    // 32768
constexpr int ATTN_SMEM  = 3 * ASTAGE_B;           // 98304

__global__ __launch_bounds__(128, 2)
void attn_mma_kernel(const float* __restrict__ Q, const float* __restrict__ K,
                     const float* __restrict__ VT, float* __restrict__ O) {
    extern __shared__ float smx[];
    const uint32_t sbase = smem_u32(smx);

    const int tid  = threadIdx.x;
    const int lane = tid & 31;
    const int wid  = tid >> 5;          // 0..3
    const int gid  = lane >> 2, tig = lane & 3;
    const int bh   = blockIdx.y;
    const int qt   = gridDim.x - 1 - blockIdx.x;   // heavy tiles first
    const int q0   = qt * AQT;

    const float* Qb  = Q  + (size_t)bh * N * A;
    const float* Kb  = K  + (size_t)bh * N * A;
    const float* VTb = VT + (size_t)bh * A * N;

    // ---- stage Q (64 rows x 512B) row-major swizzled into stage-0 alias ----
    {
        const int c16 = tid & 31;
        const int r0  = tid >> 5;       // 0..3
#pragma unroll
        for (int i = 0; i < 16; i++) {
            int row = r0 + i * 4;
            uint32_t off = (uint32_t)row * 512 + ((c16 ^ (row & 7)) << 4);
            CP_ASYNC16(sbase + off, Qb + (size_t)(q0 + row) * A + c16 * 4);
        }
        CP_COMMIT();
        CP_WAIT(0);
        __syncthreads();
    }

    // ---- Q A-frags -> registers; fold 1/sqrt(128) * log2(e) into scale ----
    const float scl = 0.08838834764831845f * 1.4426950408889634f;
    uint32_t qf[16][4];
    {
        const int a_row = wid * 16 + (lane & 15);
        const int a_hi  = lane >> 4;
#pragma unroll
        for (int kd = 0; kd < 16; kd++) {
            uint32_t addr = sbase + (uint32_t)a_row * 512
                          + (((kd * 2 + a_hi) ^ (a_row & 7)) << 4);
            ldsm_x4(qf[kd], addr);
#pragma unroll
            for (int j = 0; j < 4; j++)
                qf[kd][j] = rna_tf32_bits(__uint_as_float(qf[kd][j]) * scl);
        }
    }
    __syncthreads();   // Q smem now reusable as KV stage 0

    // ---- staging (K permuted-row; Vt d-major) ----
    const int s_c16 = tid & 31;      // K: 16B chunk in 512B row
    const int s_r0  = tid >> 5;      // K: base key row
    const int v_d0  = tid >> 3;      // Vt: base d row (0..15)
    const int v_c   = tid & 7;       // Vt: 16B chunk in 128B row
    auto stage = [&](int kt, int slot) {
        const uint32_t kb = sbase + slot * ASTAGE_B;
        const uint32_t vb = kb + K_TILE_B;
        const float* Kg  = Kb  + (size_t)(kt * AKT) * A;
        const float* VTg = VTb + (size_t)(kt * AKT) + v_c * 4;
#pragma unroll
        for (int i = 0; i < 8; i++) {
            int row  = s_r0 + i * 4;   // key index 0..31
            int prow = (row & ~7) | ((row & 3) << 1) | ((row >> 2) & 1);
            uint32_t off = (uint32_t)prow * 512 + ((s_c16 ^ (prow & 7)) << 4);
            CP_ASYNC16(kb + off, Kg + (size_t)row * A + s_c16 * 4);
        }
#pragma unroll
        for (int i = 0; i < 8; i++) {
            int d = v_d0 + i * 16;     // 0..127
            uint32_t off = (uint32_t)d * 128 + ((v_c ^ (d & 7)) << 4);
            CP_ASYNC16(vb + off, VTg + (size_t)d * N);
        }
    };

    const int nkt  = 2 * qt + 2;
    const int nktw = 2 * qt + (wid >> 1) + 1;

    float o[16][4];
#pragma unroll
    for (int nf = 0; nf < 16; nf++)
#pragma unroll
        for (int j = 0; j < 4; j++) o[nf][j] = 0.f;
    float m0 = -1e30f, m1 = -1e30f, l0 = 0.f, l1 = 0.f;

    const int row0 = q0 + wid * 16 + gid;
    const int row1 = row0 + 8;
    const int b_row = (lane & 7) + ((lane >> 4) << 3);   // 0..15
    const int b_hi  = (lane >> 3) & 1;

    stage(0, 0); CP_COMMIT();
    stage(1, 1); CP_COMMIT();

    int slot = 0;
    for (int kt = 0; kt < nkt; kt++) {
        CP_WAIT(1);
        __syncthreads();
        if (kt + 2 < nkt) {
            int ns = slot + 2; if (ns >= 3) ns -= 3;
            stage(kt + 2, ns);
        }
        CP_COMMIT();

        if (kt < nktw) {
            const uint32_t kbase = sbase + slot * ASTAGE_B;
            const uint32_t vbase = kbase + K_TILE_B;

            // ---- S = Q K^T : split accumulators + pipelined K frags ----
            float s2[2][4][4];
#pragma unroll
            for (int p = 0; p < 2; p++)
#pragma unroll
                for (int nk = 0; nk < 4; nk++)
#pragma unroll
                    for (int j = 0; j < 4; j++) s2[p][nk][j] = 0.f;

            uint32_t kfA[2][4], kfB[2][4];
            auto load_k = [&](int bufr, int kd) {
                uint32_t col = ((kd * 2 + b_hi) ^ (b_row & 7)) << 4;
                ldsm_x4(kfA[bufr], kbase + (uint32_t)b_row * 512 + col);
                ldsm_x4(kfB[bufr], kbase + (uint32_t)(b_row + 16) * 512 + col);
            };

            load_k(0, 0);
#pragma unroll
            for (int kd = 0; kd < 16; kd++) {
                const int cur = kd & 1;
                if (kd < 15) load_k(cur ^ 1, kd + 1);
                float* sp = &s2[cur][0][0];
                mma_tf32(sp + 0,  qf[kd], kfA[cur][0], kfA[cur][1]);
                mma_tf32(sp + 4,  qf[kd], kfA[cur][2], kfA[cur][3]);
                mma_tf32(sp + 8,  qf[kd], kfB[cur][0], kfB[cur][1]);
                mma_tf32(sp + 12, qf[kd], kfB[cur][2], kfB[cur][3]);
            }
            float s[4][4];
#pragma unroll
            for (int nk = 0; nk < 4; nk++)
#pragma unroll
                for (int j = 0; j < 4; j++)
                    s[nk][j] = s2[0][nk][j] + s2[1][nk][j];

            // ---- causal mask (diagonal tile only; permuted columns) ----
            if (kt == nktw - 1) {
                int colb = kt * AKT + tig;
#pragma unroll
                for (int nk = 0; nk < 4; nk++) {
                    int c0 = colb + nk * 8;
                    if (c0     > row0) s[nk][0] = -1e30f;
                    if (c0 + 4 > row0) s[nk][1] = -1e30f;
                    if (c0     > row1) s[nk][2] = -1e30f;
                    if (c0 + 4 > row1) s[nk][3] = -1e30f;
                }
            }

            // ---- online softmax (log2 domain) ----
            float mx0 = -1e30f, mx1 = -1e30f;
#pragma unroll
            for (int nk = 0; nk < 4; nk++) {
                mx0 = fmaxf(mx0, fmaxf(s[nk][0], s[nk][1]));
                mx1 = fmaxf(mx1, fmaxf(s[nk][2], s[nk][3]));
            }
            mx0 = fmaxf(mx0, __shfl_xor_sync(0xffffffffu, mx0, 1));
            mx0 = fmaxf(mx0, __shfl_xor_sync(0xffffffffu, mx0, 2));
            mx1 = fmaxf(mx1, __shfl_xor_sync(0xffffffffu, mx1, 1));
            mx1 = fmaxf(mx1, __shfl_xor_sync(0xffffffffu, mx1, 2));
            float mn0 = fmaxf(m0, mx0), mn1 = fmaxf(m1, mx1);
            float cor0 = ex2f(m0 - mn0), cor1 = ex2f(m1 - mn1);
            m0 = mn0; m1 = mn1;

            float rs0 = 0.f, rs1 = 0.f;
#pragma unroll
            for (int nk = 0; nk < 4; nk++) {
                s[nk][0] = ex2f(s[nk][0] - mn0);
                s[nk][1] = ex2f(s[nk][1] - mn0);
                s[nk][2] = ex2f(s[nk][2] - mn1);
                s[nk][3] = ex2f(s[nk][3] - mn1);
                rs0 += s[nk][0] + s[nk][1];
                rs1 += s[nk][2] + s[nk][3];
            }
            rs0 += __shfl_xor_sync(0xffffffffu, rs0, 1);
            rs0 += __shfl_xor_sync(0xffffffffu, rs0, 2);
            rs1 += __shfl_xor_sync(0xffffffffu, rs1, 1);
            rs1 += __shfl_xor_sync(0xffffffffu, rs1, 2);
            l0 = l0 * cor0 + rs0;
            l1 = l1 * cor1 + rs1;

#pragma unroll
            for (int nf = 0; nf < 16; nf++) {
                o[nf][0] *= cor0; o[nf][1] *= cor0;
                o[nf][2] *= cor1; o[nf][3] *= cor1;
            }

            // ---- P A-frags = register rename of S C-frags (natural keys) ----
            uint32_t aP[4][4];
#pragma unroll
            for (int kf = 0; kf < 4; kf++) {
                aP[kf][0] = rna_tf32_bits(s[kf][0]);
                aP[kf][1] = rna_tf32_bits(s[kf][2]);
                aP[kf][2] = rna_tf32_bits(s[kf][1]);
                aP[kf][3] = rna_tf32_bits(s[kf][3]);
            }

            // ---- O += P V : ldmatrix B-frags from d-major Vt tile ----
#pragma unroll
            for (int kf = 0; kf < 4; kf++) {
#pragma unroll
                for (int dp = 0; dp < 8; dp++) {
                    int row = dp * 16 + b_row;   // d row 0..127
                    uint32_t addr = vbase + (uint32_t)row * 128
                                  + (((kf * 2 + b_hi) ^ (row & 7)) << 4);
                    uint32_t bf[4];
                    ldsm_x4(bf, addr);
                    mma_tf32(o[2 * dp],     aP[kf], bf[0], bf[1]);
                    mma_tf32(o[2 * dp + 1], aP[kf], bf[2], bf[3]);
                }
            }
        }

        slot++; if (slot >= 3) slot = 0;
    }

    // ---- write output: [b*n, h*a], rna for Wo GEMM ----
    const float il0 = 1.f / l0, il1 = 1.f / l1;
    const int b2 = bh >> 4, h2 = bh & 15;
    float* o0 = O + (size_t)(b2 * N + row0) * HD + h2 * A;
    float* o1 = O + (size_t)(b2 * N + row1) * HD + h2 * A;
#pragma unroll
    for (int nf = 0; nf < 16; nf++) {
        int col = nf * 8 + 2 * tig;
        *(float2*)(o0 + col) = make_float2(rna_tf32(o[nf][0] * il0),
                                           rna_tf32(o[nf][1] * il0));
        *(float2*)(o1 + col) = make_float2(rna_tf32(o[nf][2] * il1),
                                           rna_tf32(o[nf][3] * il1));
    }
}

// ---------------------------------------------------------------------------
extern "C" void kernel_launch(void* const* d_in, const int* in_sizes, int n_in,
                              void* d_out, int out_size) {
    const float* q  = (const float*)d_in[0];
    const float* Wq = (const float*)d_in[1];
    const float* Wk = (const float*)d_in[2];
    const float* Wv = (const float*)d_in[3];
    const float* Wo = (const float*)d_in[4];
    float* out = (float*)d_out;

    float *qr, *Wqr, *Wkr, *Wvr, *Wor, *Qp, *Kp, *VTp, *AOp;
    cudaGetSymbolAddress((void**)&qr,  g_qr);
    cudaGetSymbolAddress((void**)&Wqr, g_Wqr);
    cudaGetSymbolAddress((void**)&Wkr, g_Wkr);
    cudaGetSymbolAddress((void**)&Wvr, g_Wvr);
    cudaGetSymbolAddress((void**)&Wor, g_Wor);
    cudaGetSymbolAddress((void**)&Qp,  g_Q);
    cudaGetSymbolAddress((void**)&Kp,  g_K);
    cudaGetSymbolAddress((void**)&VTp, g_VT);
    cudaGetSymbolAddress((void**)&AOp, g_AO);

    cudaFuncSetAttribute(qkv_gemm, cudaFuncAttributeMaxDynamicSharedMemorySize,
                         GEMM_SMEM);
    cudaFuncSetAttribute(out_gemm, cudaFuncAttributeMaxDynamicSharedMemorySize,
                         GEMM_SMEM);
    cudaFuncSetAttribute(attn_mma_kernel,
                         cudaFuncAttributeMaxDynamicSharedMemorySize, ATTN_SMEM);

    // rope sin/cos table + fused rna pre-pass (q + 4 weights)
    rope_table_kernel<<<(N * 64) / 256, 256>>>();
    {
        int total = NQ4 + 4 * NW4;   // 6,291,456
        round_all_kernel<<<total / 256, 256>>>(
            (const float4*)q, (const float4*)Wq, (const float4*)Wk,
            (const float4*)Wv, (const float4*)Wo,
            (float4*)qr, (float4*)Wqr, (float4*)Wkr, (float4*)Wvr, (float4*)Wor);
    }

    // fused QKV projections (rope fused for Q/K; V written transposed)
    qkv_gemm<<<dim3(16, 32, 3), 128, GEMM_SMEM>>>(qr, Wqr, Wkr, Wvr, Qp, Kp, VTp);

    // tensor-core causal flash attention (64q CTAs, Vt ldmatrix, 3-stage)
    attn_mma_kernel<<<dim3(N / AQT, B * H), 128, ATTN_SMEM>>>(Qp, Kp, VTp, AOp);

    // output projection
    out_gemm<<<dim3(16, 32), 128, GEMM_SMEM>>>(AOp, Wor, out);
}

// round 13
// speedup vs baseline: 2.1773x; 1.7954x over previous
#include <cuda_runtime.h>
#include <cuda_fp16.h>
#include <cstdint>
#include <math.h>

// Problem constants
constexpr int B = 2;
constexpr int H = 16;
constexpr int N = 2048;
constexpr int A = 128;           // head dim
constexpr int W = 2048;          // model width
constexpr int HD = H * A;        // 2048
constexpr int Mdim = B * N;      // 4096
constexpr int Kdim = W;          // 2048

// Scratch (device globals — no allocation allowed). All fp16.
__device__ __half g_qh [Mdim * Kdim];
__device__ __half g_Wqh[HD * W];
__device__ __half g_Wkh[HD * W];
__device__ __half g_Wvh[HD * W];
__device__ __half g_Woh[W * HD];
__device__ __half g_Qh [B * H * N * A];   // head-major, rope+scale*log2e applied
__device__ __half g_Kh [B * H * N * A];   // head-major, rope applied
__device__ __half g_VTh[B * H * A * N];   // TRANSPOSED: [b][h][d][n]
__device__ __half g_AOh[Mdim * HD];       // [b*n, h*a]
__device__ float2 g_rope[N * 64];         // (sin, cos) per (n, pair)

// ---------------------------------------------------------------------------
// helpers
// ---------------------------------------------------------------------------
__device__ __forceinline__ float ex2f(float x) {
    float y;
    asm("ex2.approx.ftz.f32 %0, %1;" : "=f"(y) : "f"(x));
    return y;
}
__device__ __forceinline__ uint32_t pack_f16x2(float lo, float hi) {
    uint32_t r;
    asm("cvt.rn.f16x2.f32 %0, %1, %2;" : "=r"(r) : "f"(hi), "f"(lo));
    return r;
}
__device__ __forceinline__ uint32_t smem_u32(const void* p) {
    uint32_t a;
    asm("{ .reg .u64 t; cvta.to.shared.u64 t, %1; cvt.u32.u64 %0, t; }"
        : "=r"(a) : "l"(p));
    return a;
}
__device__ __forceinline__ void mma_f16(float* c, const uint32_t* a,
                                        uint32_t b0, uint32_t b1) {
    asm volatile(
        "mma.sync.aligned.m16n8k16.row.col.f32.f16.f16.f32 "
        "{%0,%1,%2,%3}, {%4,%5,%6,%7}, {%8,%9}, {%0,%1,%2,%3};"
        : "+f"(c[0]), "+f"(c[1]), "+f"(c[2]), "+f"(c[3])
        : "r"(a[0]), "r"(a[1]), "r"(a[2]), "r"(a[3]), "r"(b0), "r"(b1));
}
__device__ __forceinline__ void ldsm_x4(uint32_t* r, uint32_t addr) {
    asm volatile("ldmatrix.sync.aligned.m8n8.x4.shared.b16 {%0,%1,%2,%3}, [%4];"
                 : "=r"(r[0]), "=r"(r[1]), "=r"(r[2]), "=r"(r[3]) : "r"(addr));
}
#define CP_ASYNC16(dst, src) \
    asm volatile("cp.async.cg.shared.global [%0], [%1], 16;" :: "r"(dst), "l"(src))
#define CP_COMMIT() asm volatile("cp.async.commit_group;" ::: "memory")
#define CP_WAIT(n)  asm volatile("cp.async.wait_group %0;" :: "n"(n) : "memory")

// ---------------------------------------------------------------------------
// rope sin/cos table: theta[n, i] = n * 10000^{-i/63}
// ---------------------------------------------------------------------------
__global__ void rope_table_kernel() {
    int idx = blockIdx.x * blockDim.x + threadIdx.x;   // [0, 2048*64)
    int i = idx & 63, n = idx >> 6;
    float freq = __powf(10000.0f, -(float)i * (1.0f / 63.0f));
    float s, c;
    sincosf((float)n * freq, &s, &c);
    g_rope[idx] = make_float2(s, c);
}

// ---------------------------------------------------------------------------
// fp32 -> fp16 conversion pre-pass over q + 4 weights (single launch).
// ---------------------------------------------------------------------------
constexpr int NQ4 = Mdim * Kdim / 4;   // 2,097,152
constexpr int NW4 = HD * W / 4;        // 1,048,576 = 2^20

__global__ void cvt_all_kernel(const float4* __restrict__ q,
                               const float4* __restrict__ wq,
                               const float4* __restrict__ wk,
                               const float4* __restrict__ wv,
                               const float4* __restrict__ wo,
                               __half* __restrict__ qh,
                               __half* __restrict__ wqh,
                               __half* __restrict__ wkh,
                               __half* __restrict__ wvh,
                               __half* __restrict__ woh) {
    int i = blockIdx.x * blockDim.x + threadIdx.x;
    const float4* src;
    __half* dst;
    int off;
    if (i < NQ4) {
        src = q; dst = qh; off = i;
    } else {
        int j = i - NQ4;
        int w = j >> 20;
        off = j & (NW4 - 1);
        src = (w == 0) ? wq : (w == 1) ? wk : (w == 2) ? wv : wo;
        dst = (w == 0) ? wqh : (w == 1) ? wkh : (w == 2) ? wvh : woh;
    }
    float4 v = src[off];
    uint2 p = make_uint2(pack_f16x2(v.x, v.y), pack_f16x2(v.z, v.w));
    *(uint2*)(dst + (size_t)off * 4) = p;
}

// ---------------------------------------------------------------------------
// fp16 mma.sync GEMM: C[M,Nc] = A[M,K] @ B[Nc,K]^T, m16n8k16.
// 128x128 CTA, BK=64, 128 threads, 4 warps of 64x64, 3-stage cp.async,
// XOR-swizzled 128B rows (64 fp16), ldmatrix.x4.
// OUTMODE: 0 = fp32 row-major; 1 = fp16 head-major (rope+prescale);
//          2 = fp16 head-major transposed ([b][h][d][n]).
// ---------------------------------------------------------------------------
constexpr int GTILE_B    = 128 * 128;             // 16384 B per operand (fp16)
constexpr int GSTAGE_B   = 2 * GTILE_B;           // 32768
constexpr int GEMM_SMEM  = 3 * GSTAGE_B;          // 98304

template <int OUTMODE>
__device__ __forceinline__ void gemm_body(const __half* __restrict__ Ag,
                                          const __half* __restrict__ Bg,
                                          void* __restrict__ Cg,
                                          bool doRope, float prescale) {
    extern __shared__ char gsc[];
    const uint32_t sbase = smem_u32(gsc);
    const int tid  = threadIdx.x;
    const int lane = tid & 31;
    const int wid  = tid >> 5;      // 0..3
    const int wm   = wid & 1;       // 64 rows each
    const int wn   = wid >> 1;      // 64 cols each
    const int m0   = blockIdx.y * 128;
    const int n0   = blockIdx.x * 128;

    float c[4][8][4];
#pragma unroll
    for (int mi = 0; mi < 4; mi++)
#pragma unroll
        for (int ni = 0; ni < 8; ni++)
#pragma unroll
            for (int j = 0; j < 4; j++) c[mi][ni][j] = 0.f;

    const int srow0 = tid >> 3;     // 0..15
    const int sc16  = tid & 7;
    auto stage = [&](int kt, int slot) {
        const uint32_t base = sbase + slot * GSTAGE_B;
        const __half* Asrc = Ag + (size_t)(m0 + srow0) * Kdim + kt * 64 + sc16 * 8;
        const __half* Bsrc = Bg + (size_t)(n0 + srow0) * Kdim + kt * 64 + sc16 * 8;
#pragma unroll
        for (int i = 0; i < 8; i++) {
            int row = srow0 + i * 16;
            uint32_t off = (uint32_t)row * 128 + ((sc16 ^ (row & 7)) << 4);
            CP_ASYNC16(base + off,           Asrc + (size_t)i * 16 * Kdim);
            CP_ASYNC16(base + GTILE_B + off, Bsrc + (size_t)i * 16 * Kdim);
        }
    };

    const int a_row = wm * 64 + (lane & 15);
    const int a_hi  = lane >> 4;
    const int b_row = wn * 64 + (lane & 7) + ((lane >> 4) << 3);
    const int b_hi  = (lane >> 3) & 1;

    stage(0, 0); CP_COMMIT();
    stage(1, 1); CP_COMMIT();

    constexpr int NKT = Kdim / 64;   // 32
    int slot = 0;
    for (int kt = 0; kt < NKT; kt++) {
        CP_WAIT(1);
        __syncthreads();
        if (kt + 2 < NKT) {
            int ns = slot + 2; if (ns >= 3) ns -= 3;
            stage(kt + 2, ns);
        }
        CP_COMMIT();

        const uint32_t abase = sbase + slot * GSTAGE_B;
        const uint32_t bbase = abase + GTILE_B;
#pragma unroll
        for (int ks = 0; ks < 4; ks++) {   // k16 steps
            uint32_t af[4][4];
#pragma unroll
            for (int mi = 0; mi < 4; mi++) {
                int row = a_row + mi * 16;
                uint32_t addr = abase + (uint32_t)row * 128
                              + (((ks * 2 + a_hi) ^ (row & 7)) << 4);
                ldsm_x4(af[mi], addr);
            }
#pragma unroll
            for (int nip = 0; nip < 4; nip++) {
                int row = b_row + nip * 16;
                uint32_t addr = bbase + (uint32_t)row * 128
                              + (((ks * 2 + b_hi) ^ (row & 7)) << 4);
                uint32_t bf[4];
                ldsm_x4(bf, addr);
#pragma unroll
                for (int mi = 0; mi < 4; mi++) {
                    mma_f16(c[mi][2 * nip],     af[mi], bf[0], bf[1]);
                    mma_f16(c[mi][2 * nip + 1], af[mi], bf[2], bf[3]);
                }
            }
        }
        slot++; if (slot >= 3) slot = 0;
    }

    const int gid = lane >> 2, tig = lane & 3;
#pragma unroll
    for (int mi = 0; mi < 4; mi++) {
#pragma unroll
        for (int ni = 0; ni < 8; ni++) {
            int n = n0 + wn * 64 + ni * 8 + tig * 2;
#pragma unroll
            for (int half2i = 0; half2i < 2; half2i++) {
                int m = m0 + wm * 64 + mi * 16 + gid + half2i * 8;
                float2 v = make_float2(c[mi][ni][half2i * 2],
                                       c[mi][ni][half2i * 2 + 1]);
                if (OUTMODE == 0) {
                    *(float2*)((float*)Cg + (size_t)m * 2048 + n) = v;
                } else {
                    if (doRope) {
                        int pi   = (n & 127) >> 1;
                        int npos = m & 2047;
                        float2 sc = g_rope[(npos << 6) + pi];
                        float ev = v.x * sc.y - v.y * sc.x;
                        float ov = v.y * sc.y + v.x * sc.x;
                        v = make_float2(ev, ov);
                    }
                    v.x *= prescale; v.y *= prescale;
                    int b2 = m >> 11, np = m & 2047, h2 = n >> 7, a0 = n & 127;
                    if (OUTMODE == 2) {
                        __half* p = (__half*)Cg
                                  + (((size_t)b2 * H + h2) * A + a0) * N + np;
                        p[0] = __float2half_rn(v.x);
                        p[N] = __float2half_rn(v.y);
                    } else {
                        uint32_t pk = pack_f16x2(v.x, v.y);
                        *(uint32_t*)((__half*)Cg
                            + ((((size_t)b2 * H + h2) * N) + np) * A + a0) = pk;
                    }
                }
            }
        }
    }
}

// Q/K/V fused projections. z=0: Q (rope + scale*log2e), z=1: K (rope),
// z=2: V (transposed store).
__global__ __launch_bounds__(128, 2)
void qkv_gemm(const __half* __restrict__ q,
              const __half* __restrict__ Wq, const __half* __restrict__ Wk,
              const __half* __restrict__ Wv,
              __half* __restrict__ Qp, __half* __restrict__ Kp,
              __half* __restrict__ VTp) {
    const int z = blockIdx.z;
    const float QSCL = 0.08838834764831845f * 1.4426950408889634f;
    if (z == 0)      gemm_body<1>(q, Wq, Qp,  true,  QSCL);
    else if (z == 1) gemm_body<1>(q, Wk, Kp,  true,  1.0f);
    else             gemm_body<2>(q, Wv, VTp, false, 1.0f);
}

__global__ __launch_bounds__(128, 2)
void out_gemm(const __half* __restrict__ Ag, const __half* __restrict__ Bg,
              float* __restrict__ Cg) {
    gemm_body<0>(Ag, Bg, Cg, false, 1.0f);
}

// ---------------------------------------------------------------------------
// fp16 tensor-core causal flash attention v8.
// CTA: 64 queries, 128 threads (4 warps x 16 q rows), 64-key tiles, 3-stage.
// K: [key][d] 256B swizzled rows + ldmatrix. Vt: [d][key] 128B swizzled rows
// + ldmatrix. Q pre-scaled (1/sqrt(d)*log2e) fp16 -> register A-frags.
// fp16 A-frag packing makes P == S C-frags via cvt.rn.f16x2 (no transpose).
// ---------------------------------------------------------------------------
constexpr int AQT = 64;
constexpr int AKT = 64;
constexpr int K_TILE_B   = AKT * 256;              // 16384 (64 rows x 256B)
constexpr int V_TILE_B   = 128 * 128;              // 16384 (128 rows x 128B)
constexpr int ASTAGE_B   = K_TILE_B + V_TILE_B;    // 32768
constexpr int ATTN_SMEM  = 3 * ASTAGE_B;           // 98304

__global__ __launch_bounds__(128, 2)
void attn_mma_kernel(const __half* __restrict__ Q, const __half* __restrict__ K,
                     const __half* __restrict__ VT, __half* __restrict__ O) {
    extern __shared__ char smc[];
    const uint32_t sbase = smem_u32(smc);

    const int tid  = threadIdx.x;
    const int lane = tid & 31;
    const int wid  = tid >> 5;          // 0..3
    const int gid  = lane >> 2, tig = lane & 3;
    const int bh   = blockIdx.y;
    const int qt   = gridDim.x - 1 - blockIdx.x;   // heavy tiles first
    const int q0   = qt * AQT;

    const __half* Qb  = Q  + (size_t)bh * N * A;
    const __half* Kb  = K  + (size_t)bh * N * A;
    const __half* VTb = VT + (size_t)bh * A * N;

    // ---- stage Q (64 rows x 256B) into stage-0 alias ----
    {
#pragma unroll
        for (int i = 0; i < 8; i++) {
            int cidx = tid + i * 128;          // 0..1023
            int row = cidx >> 4, ch = cidx & 15;
            uint32_t off = (uint32_t)row * 256 + ((ch ^ (row & 7)) << 4);
            CP_ASYNC16(sbase + off, Qb + (size_t)(q0 + row) * A + ch * 8);
        }
        CP_COMMIT();
        CP_WAIT(0);
        __syncthreads();
    }

    // ---- Q A-frags -> registers (already scaled in projection) ----
    uint32_t qf[8][4];
    {
        const int a_row = wid * 16 + (lane & 15);
        const int a_hi  = lane >> 4;
#pragma unroll
        for (int kd = 0; kd < 8; kd++) {
            uint32_t addr = sbase + (uint32_t)a_row * 256
                          + (((kd * 2 + a_hi) ^ (a_row & 7)) << 4);
            ldsm_x4(qf[kd], addr);
        }
    }
    __syncthreads();   // Q smem now reusable as KV stage 0

    // ---- KV staging ----
    auto stage = [&](int kt, int slot) {
        const uint32_t kb = sbase + slot * ASTAGE_B;
        const uint32_t vb = kb + K_TILE_B;
        const __half* Kg  = Kb  + (size_t)(kt * AKT) * A;
        const __half* VTg = VTb + (size_t)(kt * AKT);
#pragma unroll
        for (int i = 0; i < 8; i++) {
            int cidx = tid + i * 128;
            int row = cidx >> 4, ch = cidx & 15;
            uint32_t off = (uint32_t)row * 256 + ((ch ^ (row & 7)) << 4);
            CP_ASYNC16(kb + off, Kg + (size_t)row * A + ch * 8);
        }
#pragma unroll
        for (int i = 0; i < 8; i++) {
            int cidx = tid + i * 128;
            int row = cidx >> 3, ch = cidx & 7;   // d row, key chunk
            uint32_t off = (uint32_t)row * 128 + ((ch ^ (row & 7)) << 4);
            CP_ASYNC16(vb + off, VTg + (size_t)row * N + ch * 8);
        }
    };

    const int nkt = qt + 1;

    float o[16][4];
#pragma unroll
    for (int nf = 0; nf < 16; nf++)
#pragma unroll
        for (int j = 0; j < 4; j++) o[nf][j] = 0.f;
    float m0 = -1e30f, m1 = -1e30f, l0 = 0.f, l1 = 0.f;

    const int row0 = q0 + wid * 16 + gid;
    const int row1 = row0 + 8;
    const int b_row = (lane & 7) + ((lane >> 4) << 3);   // 0..15
    const int b_hi  = (lane >> 3) & 1;

    stage(0, 0); CP_COMMIT();
    if (nkt > 1) { stage(1, 1); } CP_COMMIT();

    int slot = 0;
    for (int kt = 0; kt < nkt; kt++) {
        CP_WAIT(1);
        __syncthreads();
        if (kt + 2 < nkt) {
            int ns = slot + 2; if (ns >= 3) ns -= 3;
            stage(kt + 2, ns);
        }
        CP_COMMIT();

        const uint32_t kbase = sbase + slot * ASTAGE_B;
        const uint32_t vbase = kbase + K_TILE_B;

        // ---- S = Q K^T (64 keys = 8 n-groups) ----
        float s[8][4];
#pragma unroll
        for (int nk = 0; nk < 8; nk++)
#pragma unroll
            for (int j = 0; j < 4; j++) s[nk][j] = 0.f;

#pragma unroll
        for (int kd = 0; kd < 8; kd++) {
#pragma unroll
            for (int g = 0; g < 4; g++) {
                int row = b_row + g * 16;
                uint32_t addr = kbase + (uint32_t)row * 256
                              + (((kd * 2 + b_hi) ^ (row & 7)) << 4);
                uint32_t bf[4];
                ldsm_x4(bf, addr);
                mma_f16(s[2 * g],     qf[kd], bf[0], bf[1]);
                mma_f16(s[2 * g + 1], qf[kd], bf[2], bf[3]);
            }
        }

        // ---- causal mask (diagonal tile only) ----
        if (kt == nkt - 1) {
            int colb = kt * AKT + 2 * tig;
#pragma unroll
            for (int nk = 0; nk < 8; nk++) {
                int c0 = colb + nk * 8;
                if (c0     > row0) s[nk][0] = -1e30f;
                if (c0 + 1 > row0) s[nk][1] = -1e30f;
                if (c0     > row1) s[nk][2] = -1e30f;
                if (c0 + 1 > row1) s[nk][3] = -1e30f;
            }
        }

        // ---- online softmax (log2 domain) ----
        float mx0 = -1e30f, mx1 = -1e30f;
#pragma unroll
        for (int nk = 0; nk < 8; nk++) {
            mx0 = fmaxf(mx0, fmaxf(s[nk][0], s[nk][1]));
            mx1 = fmaxf(mx1, fmaxf(s[nk][2], s[nk][3]));
        }
        mx0 = fmaxf(mx0, __shfl_xor_sync(0xffffffffu, mx0, 1));
        mx0 = fmaxf(mx0, __shfl_xor_sync(0xffffffffu, mx0, 2));
        mx1 = fmaxf(mx1, __shfl_xor_sync(0xffffffffu, mx1, 1));
        mx1 = fmaxf(mx1, __shfl_xor_sync(0xffffffffu, mx1, 2));
        float mn0 = fmaxf(m0, mx0), mn1 = fmaxf(m1, mx1);
        float cor0 = ex2f(m0 - mn0), cor1 = ex2f(m1 - mn1);
        m0 = mn0; m1 = mn1;

        float rs0 = 0.f, rs1 = 0.f;
#pragma unroll
        for (int nk = 0; nk < 8; nk++) {
            s[nk][0] = ex2f(s[nk][0] - mn0);
            s[nk][1] = ex2f(s[nk][1] - mn0);
            s[nk][2] = ex2f(s[nk][2] - mn1);
            s[nk][3] = ex2f(s[nk][3] - mn1);
            rs0 += s[nk][0] + s[nk][1];
            rs1 += s[nk][2] + s[nk][3];
        }
        rs0 += __shfl_xor_sync(0xffffffffu, rs0, 1);
        rs0 += __shfl_xor_sync(0xffffffffu, rs0, 2);
        rs1 += __shfl_xor_sync(0xffffffffu, rs1, 1);
        rs1 += __shfl_xor_sync(0xffffffffu, rs1, 2);
        l0 = l0 * cor0 + rs0;
        l1 = l1 * cor1 + rs1;

#pragma unroll
        for (int nf = 0; nf < 16; nf++) {
            o[nf][0] *= cor0; o[nf][1] *= cor0;
            o[nf][2] *= cor1; o[nf][3] *= cor1;
        }

        // ---- P A-frags: fp16x2 packs of S C-frags (no transpose needed) ----
        uint32_t aP[4][4];
#pragma unroll
        for (int kf = 0; kf < 4; kf++) {
            aP[kf][0] = pack_f16x2(s[2 * kf][0],     s[2 * kf][1]);
            aP[kf][1] = pack_f16x2(s[2 * kf][2],     s[2 * kf][3]);
            aP[kf][2] = pack_f16x2(s[2 * kf + 1][0], s[2 * kf + 1][1]);
            aP[kf][3] = pack_f16x2(s[2 * kf + 1][2], s[2 * kf + 1][3]);
        }

        // ---- O += P V : ldmatrix B-frags from d-major Vt tile ----
#pragma unroll
        for (int kf = 0; kf < 4; kf++) {
#pragma unroll
            for (int dp = 0; dp < 8; dp++) {
                int row = dp * 16 + b_row;   // d row 0..127
                uint32_t addr = vbase + (uint32_t)row * 128
                              + (((kf * 2 + b_hi) ^ (row & 7)) << 4);
                uint32_t bf[4];
                ldsm_x4(bf, addr);
                mma_f16(o[2 * dp],     aP[kf], bf[0], bf[1]);
                mma_f16(o[2 * dp + 1], aP[kf], bf[2], bf[3]);
            }
        }

        slot++; if (slot >= 3) slot = 0;
    }

    // ---- write output: fp16 [b*n, h*a] ----
    const float il0 = 1.f / l0, il1 = 1.f / l1;
    const int b2 = bh >> 4, h2 = bh & 15;
    __half* o0 = O + (size_t)(b2 * N + row0) * HD + h2 * A;
    __half* o1 = O + (size_t)(b2 * N + row1) * HD + h2 * A;
#pragma unroll
    for (int nf = 0; nf < 16; nf++) {
        int col = nf * 8 + 2 * tig;
        *(uint32_t*)(o0 + col) = pack_f16x2(o[nf][0] * il0, o[nf][1] * il0);
        *(uint32_t*)(o1 + col) = pack_f16x2(o[nf][2] * il1, o[nf][3] * il1);
    }
}

// ---------------------------------------------------------------------------
extern "C" void kernel_launch(void* const* d_in, const int* in_sizes, int n_in,
                              void* d_out, int out_size) {
    const float* q  = (const float*)d_in[0];
    const float* Wq = (const float*)d_in[1];
    const float* Wk = (const float*)d_in[2];
    const float* Wv = (const float*)d_in[3];
    const float* Wo = (const float*)d_in[4];
    float* out = (float*)d_out;

    __half *qh, *Wqh, *Wkh, *Wvh, *Woh, *Qh, *Kh, *VTh, *AOh;
    cudaGetSymbolAddress((void**)&qh,  g_qh);
    cudaGetSymbolAddress((void**)&Wqh, g_Wqh);
    cudaGetSymbolAddress((void**)&Wkh, g_Wkh);
    cudaGetSymbolAddress((void**)&Wvh, g_Wvh);
    cudaGetSymbolAddress((void**)&Woh, g_Woh);
    cudaGetSymbolAddress((void**)&Qh,  g_Qh);
    cudaGetSymbolAddress((void**)&Kh,  g_Kh);
    cudaGetSymbolAddress((void**)&VTh, g_VTh);
    cudaGetSymbolAddress((void**)&AOh, g_AOh);

    cudaFuncSetAttribute(qkv_gemm, cudaFuncAttributeMaxDynamicSharedMemorySize,
                         GEMM_SMEM);
    cudaFuncSetAttribute(out_gemm, cudaFuncAttributeMaxDynamicSharedMemorySize,
                         GEMM_SMEM);
    cudaFuncSetAttribute(attn_mma_kernel,
                         cudaFuncAttributeMaxDynamicSharedMemorySize, ATTN_SMEM);

    // rope sin/cos table + fp16 conversion pre-pass (q + 4 weights)
    rope_table_kernel<<<(N * 64) / 256, 256>>>();
    {
        int total = NQ4 + 4 * NW4;   // 6,291,456
        cvt_all_kernel<<<total / 256, 256>>>(
            (const float4*)q, (const float4*)Wq, (const float4*)Wk,
            (const float4*)Wv, (const float4*)Wo,
            qh, Wqh, Wkh, Wvh, Woh);
    }

    // fused QKV projections (rope + scale fused; V stored transposed)
    qkv_gemm<<<dim3(16, 32, 3), 128, GEMM_SMEM>>>(qh, Wqh, Wkh, Wvh, Qh, Kh, VTh);

    // fp16 tensor-core causal flash attention (64q CTAs, 64-key tiles)
    attn_mma_kernel<<<dim3(N / AQT, B * H), 128, ATTN_SMEM>>>(Qh, Kh, VTh, AOh);

    // output projection (fp32 result)
    out_gemm<<<dim3(16, 32), 128, GEMM_SMEM>>>(AOh, Woh, out);
}

// round 14
// speedup vs baseline: 2.2178x; 1.0186x over previous
#include <cuda_runtime.h>
#include <cuda_fp16.h>
#include <cstdint>
#include <math.h>

// Problem constants
constexpr int B = 2;
constexpr int H = 16;
constexpr int N = 2048;
constexpr int A = 128;           // head dim
constexpr int W = 2048;          // model width
constexpr int HD = H * A;        // 2048
constexpr int Mdim = B * N;      // 4096
constexpr int Kdim = W;          // 2048

// Scratch (device globals — no allocation allowed). All fp16.
__device__ __half g_qh [Mdim * Kdim];
__device__ __half g_Wqh[HD * W];
__device__ __half g_Wkh[HD * W];
__device__ __half g_Wvh[HD * W];
__device__ __half g_Woh[W * HD];
__device__ __half g_Qh [B * H * N * A];   // head-major, rope+scale*log2e applied
__device__ __half g_Kh [B * H * N * A];   // head-major, rope applied
__device__ __half g_VTh[B * H * A * N];   // TRANSPOSED: [b][h][d][n]
__device__ __half g_AOh[Mdim * HD];       // [b*n, h*a]
__device__ float2 g_rope[N * 64];         // (sin, cos) per (n, pair)

// ---------------------------------------------------------------------------
// helpers
// ---------------------------------------------------------------------------
__device__ __forceinline__ float ex2f(float x) {
    float y;
    asm("ex2.approx.ftz.f32 %0, %1;" : "=f"(y) : "f"(x));
    return y;
}
__device__ __forceinline__ uint32_t pack_f16x2(float lo, float hi) {
    uint32_t r;
    asm("cvt.rn.f16x2.f32 %0, %1, %2;" : "=r"(r) : "f"(hi), "f"(lo));
    return r;
}
__device__ __forceinline__ uint32_t smem_u32(const void* p) {
    uint32_t a;
    asm("{ .reg .u64 t; cvta.to.shared.u64 t, %1; cvt.u32.u64 %0, t; }"
        : "=r"(a) : "l"(p));
    return a;
}
__device__ __forceinline__ void mma_f16(float* c, const uint32_t* a,
                                        uint32_t b0, uint32_t b1) {
    asm volatile(
        "mma.sync.aligned.m16n8k16.row.col.f32.f16.f16.f32 "
        "{%0,%1,%2,%3}, {%4,%5,%6,%7}, {%8,%9}, {%0,%1,%2,%3};"
        : "+f"(c[0]), "+f"(c[1]), "+f"(c[2]), "+f"(c[3])
        : "r"(a[0]), "r"(a[1]), "r"(a[2]), "r"(a[3]), "r"(b0), "r"(b1));
}
__device__ __forceinline__ void ldsm_x4(uint32_t* r, uint32_t addr) {
    asm volatile("ldmatrix.sync.aligned.m8n8.x4.shared.b16 {%0,%1,%2,%3}, [%4];"
                 : "=r"(r[0]), "=r"(r[1]), "=r"(r[2]), "=r"(r[3]) : "r"(addr));
}
#define CP_ASYNC16(dst, src) \
    asm volatile("cp.async.cg.shared.global [%0], [%1], 16;" :: "r"(dst), "l"(src))
#define CP_COMMIT() asm volatile("cp.async.commit_group;" ::: "memory")
#define CP_WAIT(n)  asm volatile("cp.async.wait_group %0;" :: "n"(n) : "memory")

// ---------------------------------------------------------------------------
// rope sin/cos table: theta[n, i] = n * 10000^{-i/63}
// ---------------------------------------------------------------------------
__global__ void rope_table_kernel() {
    int idx = blockIdx.x * blockDim.x + threadIdx.x;   // [0, 2048*64)
    int i = idx & 63, n = idx >> 6;
    float freq = __powf(10000.0f, -(float)i * (1.0f / 63.0f));
    float s, c;
    sincosf((float)n * freq, &s, &c);
    g_rope[idx] = make_float2(s, c);
}

// ---------------------------------------------------------------------------
// fp32 -> fp16 conversion pre-pass over q + 4 weights (single launch).
// ---------------------------------------------------------------------------
constexpr int NQ4 = Mdim * Kdim / 4;   // 2,097,152
constexpr int NW4 = HD * W / 4;        // 1,048,576 = 2^20

__global__ void cvt_all_kernel(const float4* __restrict__ q,
                               const float4* __restrict__ wq,
                               const float4* __restrict__ wk,
                               const float4* __restrict__ wv,
                               const float4* __restrict__ wo,
                               __half* __restrict__ qh,
                               __half* __restrict__ wqh,
                               __half* __restrict__ wkh,
                               __half* __restrict__ wvh,
                               __half* __restrict__ woh) {
    int i = blockIdx.x * blockDim.x + threadIdx.x;
    const float4* src;
    __half* dst;
    int off;
    if (i < NQ4) {
        src = q; dst = qh; off = i;
    } else {
        int j = i - NQ4;
        int w = j >> 20;
        off = j & (NW4 - 1);
        src = (w == 0) ? wq : (w == 1) ? wk : (w == 2) ? wv : wo;
        dst = (w == 0) ? wqh : (w == 1) ? wkh : (w == 2) ? wvh : woh;
    }
    float4 v = src[off];
    uint2 p = make_uint2(pack_f16x2(v.x, v.y), pack_f16x2(v.z, v.w));
    *(uint2*)(dst + (size_t)off * 4) = p;
}

// ---------------------------------------------------------------------------
// fp16 mma.sync GEMM v2: C[M,Nc] = A[M,K] @ B[Nc,K]^T, m16n8k16.
// 128x128 CTA, BK=64, 256 threads, 8 warps of 64x32 (2m x 4n),
// 3-stage cp.async, XOR-swizzled 128B rows, ldmatrix.x4.
// 2 CTAs/SM -> 4 warps/SMSP (latency hiding doubled vs 4-warp version).
// OUTMODE: 0 = fp32 row-major; 1 = fp16 head-major (rope+prescale);
//          2 = fp16 head-major transposed ([b][h][d][n]).
// ---------------------------------------------------------------------------
constexpr int GTILE_B    = 128 * 128;             // 16384 B per operand (fp16)
constexpr int GSTAGE_B   = 2 * GTILE_B;           // 32768
constexpr int GEMM_SMEM  = 3 * GSTAGE_B;          // 98304

template <int OUTMODE>
__device__ __forceinline__ void gemm_body(const __half* __restrict__ Ag,
                                          const __half* __restrict__ Bg,
                                          void* __restrict__ Cg,
                                          bool doRope, float prescale) {
    extern __shared__ char gsc[];
    const uint32_t sbase = smem_u32(gsc);
    const int tid  = threadIdx.x;
    const int lane = tid & 31;
    const int wid  = tid >> 5;      // 0..7
    const int wm   = wid & 1;       // 64 rows each
    const int wn   = wid >> 1;      // 32 cols each (0..3)
    const int m0   = blockIdx.y * 128;
    const int n0   = blockIdx.x * 128;

    float c[4][4][4];
#pragma unroll
    for (int mi = 0; mi < 4; mi++)
#pragma unroll
        for (int ni = 0; ni < 4; ni++)
#pragma unroll
            for (int j = 0; j < 4; j++) c[mi][ni][j] = 0.f;

    // staging: 1024 16B-chunks per operand, 4 per thread
    auto stage = [&](int kt, int slot) {
        const uint32_t base = sbase + slot * GSTAGE_B;
#pragma unroll
        for (int i = 0; i < 4; i++) {
            int cidx = tid + i * 256;
            int row = cidx >> 3, ch = cidx & 7;
            uint32_t off = (uint32_t)row * 128 + ((ch ^ (row & 7)) << 4);
            CP_ASYNC16(base + off,
                       Ag + (size_t)(m0 + row) * Kdim + kt * 64 + ch * 8);
            CP_ASYNC16(base + GTILE_B + off,
                       Bg + (size_t)(n0 + row) * Kdim + kt * 64 + ch * 8);
        }
    };

    const int a_row = wm * 64 + (lane & 15);
    const int a_hi  = lane >> 4;
    const int b_row = wn * 32 + (lane & 7) + ((lane >> 4) << 3);
    const int b_hi  = (lane >> 3) & 1;

    stage(0, 0); CP_COMMIT();
    stage(1, 1); CP_COMMIT();

    constexpr int NKT = Kdim / 64;   // 32
    int slot = 0;
    for (int kt = 0; kt < NKT; kt++) {
        CP_WAIT(1);
        __syncthreads();
        if (kt + 2 < NKT) {
            int ns = slot + 2; if (ns >= 3) ns -= 3;
            stage(kt + 2, ns);
        }
        CP_COMMIT();

        const uint32_t abase = sbase + slot * GSTAGE_B;
        const uint32_t bbase = abase + GTILE_B;
#pragma unroll
        for (int ks = 0; ks < 4; ks++) {   // k16 steps
            uint32_t af[4][4];
#pragma unroll
            for (int mi = 0; mi < 4; mi++) {
                int row = a_row + mi * 16;
                uint32_t addr = abase + (uint32_t)row * 128
                              + (((ks * 2 + a_hi) ^ (row & 7)) << 4);
                ldsm_x4(af[mi], addr);
            }
#pragma unroll
            for (int nip = 0; nip < 2; nip++) {
                int row = b_row + nip * 16;
                uint32_t addr = bbase + (uint32_t)row * 128
                              + (((ks * 2 + b_hi) ^ (row & 7)) << 4);
                uint32_t bf[4];
                ldsm_x4(bf, addr);
#pragma unroll
                for (int mi = 0; mi < 4; mi++) {
                    mma_f16(c[mi][2 * nip],     af[mi], bf[0], bf[1]);
                    mma_f16(c[mi][2 * nip + 1], af[mi], bf[2], bf[3]);
                }
            }
        }
        slot++; if (slot >= 3) slot = 0;
    }

    const int gid = lane >> 2, tig = lane & 3;
#pragma unroll
    for (int mi = 0; mi < 4; mi++) {
#pragma unroll
        for (int ni = 0; ni < 4; ni++) {
            int n = n0 + wn * 32 + ni * 8 + tig * 2;
#pragma unroll
            for (int half2i = 0; half2i < 2; half2i++) {
                int m = m0 + wm * 64 + mi * 16 + gid + half2i * 8;
                float2 v = make_float2(c[mi][ni][half2i * 2],
                                       c[mi][ni][half2i * 2 + 1]);
                if (OUTMODE == 0) {
                    *(float2*)((float*)Cg + (size_t)m * 2048 + n) = v;
                } else {
                    if (doRope) {
                        int pi   = (n & 127) >> 1;
                        int npos = m & 2047;
                        float2 sc = g_rope[(npos << 6) + pi];
                        float ev = v.x * sc.y - v.y * sc.x;
                        float ov = v.y * sc.y + v.x * sc.x;
                        v = make_float2(ev, ov);
                    }
                    v.x *= prescale; v.y *= prescale;
                    int b2 = m >> 11, np = m & 2047, h2 = n >> 7, a0 = n & 127;
                    if (OUTMODE == 2) {
                        __half* p = (__half*)Cg
                                  + (((size_t)b2 * H + h2) * A + a0) * N + np;
                        p[0] = __float2half_rn(v.x);
                        p[N] = __float2half_rn(v.y);
                    } else {
                        uint32_t pk = pack_f16x2(v.x, v.y);
                        *(uint32_t*)((__half*)Cg
                            + ((((size_t)b2 * H + h2) * N) + np) * A + a0) = pk;
                    }
                }
            }
        }
    }
}

// Q/K/V fused projections. z=0: Q (rope + scale*log2e), z=1: K (rope),
// z=2: V (transposed store).
__global__ __launch_bounds__(256, 2)
void qkv_gemm(const __half* __restrict__ q,
              const __half* __restrict__ Wq, const __half* __restrict__ Wk,
              const __half* __restrict__ Wv,
              __half* __restrict__ Qp, __half* __restrict__ Kp,
              __half* __restrict__ VTp) {
    const int z = blockIdx.z;
    const float QSCL = 0.08838834764831845f * 1.4426950408889634f;
    if (z == 0)      gemm_body<1>(q, Wq, Qp,  true,  QSCL);
    else if (z == 1) gemm_body<1>(q, Wk, Kp,  true,  1.0f);
    else             gemm_body<2>(q, Wv, VTp, false, 1.0f);
}

__global__ __launch_bounds__(256, 2)
void out_gemm(const __half* __restrict__ Ag, const __half* __restrict__ Bg,
              float* __restrict__ Cg) {
    gemm_body<0>(Ag, Bg, Cg, false, 1.0f);
}

// ---------------------------------------------------------------------------
// fp16 tensor-core causal flash attention (unchanged from R13).
// CTA: 64 queries, 128 threads (4 warps x 16 q rows), 64-key tiles, 3-stage.
// ---------------------------------------------------------------------------
constexpr int AQT = 64;
constexpr int AKT = 64;
constexpr int K_TILE_B   = AKT * 256;              // 16384 (64 rows x 256B)
constexpr int V_TILE_B   = 128 * 128;              // 16384 (128 rows x 128B)
constexpr int ASTAGE_B   = K_TILE_B + V_TILE_B;    // 32768
constexpr int ATTN_SMEM  = 3 * ASTAGE_B;           // 98304

__global__ __launch_bounds__(128, 2)
void attn_mma_kernel(const __half* __restrict__ Q, const __half* __restrict__ K,
                     const __half* __restrict__ VT, __half* __restrict__ O) {
    extern __shared__ char smc[];
    const uint32_t sbase = smem_u32(smc);

    const int tid  = threadIdx.x;
    const int lane = tid & 31;
    const int wid  = tid >> 5;          // 0..3
    const int gid  = lane >> 2, tig = lane & 3;
    const int bh   = blockIdx.y;
    const int qt   = gridDim.x - 1 - blockIdx.x;   // heavy tiles first
    const int q0   = qt * AQT;

    const __half* Qb  = Q  + (size_t)bh * N * A;
    const __half* Kb  = K  + (size_t)bh * N * A;
    const __half* VTb = VT + (size_t)bh * A * N;

    // ---- stage Q (64 rows x 256B) into stage-0 alias ----
    {
#pragma unroll
        for (int i = 0; i < 8; i++) {
            int cidx = tid + i * 128;          // 0..1023
            int row = cidx >> 4, ch = cidx & 15;
            uint32_t off = (uint32_t)row * 256 + ((ch ^ (row & 7)) << 4);
            CP_ASYNC16(sbase + off, Qb + (size_t)(q0 + row) * A + ch * 8);
        }
        CP_COMMIT();
        CP_WAIT(0);
        __syncthreads();
    }

    // ---- Q A-frags -> registers (already scaled in projection) ----
    uint32_t qf[8][4];
    {
        const int a_row = wid * 16 + (lane & 15);
        const int a_hi  = lane >> 4;
#pragma unroll
        for (int kd = 0; kd < 8; kd++) {
            uint32_t addr = sbase + (uint32_t)a_row * 256
                          + (((kd * 2 + a_hi) ^ (a_row & 7)) << 4);
            ldsm_x4(qf[kd], addr);
        }
    }
    __syncthreads();   // Q smem now reusable as KV stage 0

    // ---- KV staging ----
    auto stage = [&](int kt, int slot) {
        const uint32_t kb = sbase + slot * ASTAGE_B;
        const uint32_t vb = kb + K_TILE_B;
        const __half* Kg  = Kb  + (size_t)(kt * AKT) * A;
        const __half* VTg = VTb + (size_t)(kt * AKT);
#pragma unroll
        for (int i = 0; i < 8; i++) {
            int cidx = tid + i * 128;
            int row = cidx >> 4, ch = cidx & 15;
            uint32_t off = (uint32_t)row * 256 + ((ch ^ (row & 7)) << 4);
            CP_ASYNC16(kb + off, Kg + (size_t)row * A + ch * 8);
        }
#pragma unroll
        for (int i = 0; i < 8; i++) {
            int cidx = tid + i * 128;
            int row = cidx >> 3, ch = cidx & 7;   // d row, key chunk
            uint32_t off = (uint32_t)row * 128 + ((ch ^ (row & 7)) << 4);
            CP_ASYNC16(vb + off, VTg + (size_t)row * N + ch * 8);
        }
    };

    const int nkt = qt + 1;

    float o[16][4];
#pragma unroll
    for (int nf = 0; nf < 16; nf++)
#pragma unroll
        for (int j = 0; j < 4; j++) o[nf][j] = 0.f;
    float m0 = -1e30f, m1 = -1e30f, l0 = 0.f, l1 = 0.f;

    const int row0 = q0 + wid * 16 + gid;
    const int row1 = row0 + 8;
    const int b_row = (lane & 7) + ((lane >> 4) << 3);   // 0..15
    const int b_hi  = (lane >> 3) & 1;

    stage(0, 0); CP_COMMIT();
    if (nkt > 1) { stage(1, 1); } CP_COMMIT();

    int slot = 0;
    for (int kt = 0; kt < nkt; kt++) {
        CP_WAIT(1);
        __syncthreads();
        if (kt + 2 < nkt) {
            int ns = slot + 2; if (ns >= 3) ns -= 3;
            stage(kt + 2, ns);
        }
        CP_COMMIT();

        const uint32_t kbase = sbase + slot * ASTAGE_B;
        const uint32_t vbase = kbase + K_TILE_B;

        // ---- S = Q K^T (64 keys = 8 n-groups) ----
        float s[8][4];
#pragma unroll
        for (int nk = 0; nk < 8; nk++)
#pragma unroll
            for (int j = 0; j < 4; j++) s[nk][j] = 0.f;

#pragma unroll
        for (int kd = 0; kd < 8; kd++) {
#pragma unroll
            for (int g = 0; g < 4; g++) {
                int row = b_row + g * 16;
                uint32_t addr = kbase + (uint32_t)row * 256
                              + (((kd * 2 + b_hi) ^ (row & 7)) << 4);
                uint32_t bf[4];
                ldsm_x4(bf, addr);
                mma_f16(s[2 * g],     qf[kd], bf[0], bf[1]);
                mma_f16(s[2 * g + 1], qf[kd], bf[2], bf[3]);
            }
        }

        // ---- causal mask (diagonal tile only) ----
        if (kt == nkt - 1) {
            int colb = kt * AKT + 2 * tig;
#pragma unroll
            for (int nk = 0; nk < 8; nk++) {
                int c0 = colb + nk * 8;
                if (c0     > row0) s[nk][0] = -1e30f;
                if (c0 + 1 > row0) s[nk][1] = -1e30f;
                if (c0     > row1) s[nk][2] = -1e30f;
                if (c0 + 1 > row1) s[nk][3] = -1e30f;
            }
        }

        // ---- online softmax (log2 domain) ----
        float mx0 = -1e30f, mx1 = -1e30f;
#pragma unroll
        for (int nk = 0; nk < 8; nk++) {
            mx0 = fmaxf(mx0, fmaxf(s[nk][0], s[nk][1]));
            mx1 = fmaxf(mx1, fmaxf(s[nk][2], s[nk][3]));
        }
        mx0 = fmaxf(mx0, __shfl_xor_sync(0xffffffffu, mx0, 1));
        mx0 = fmaxf(mx0, __shfl_xor_sync(0xffffffffu, mx0, 2));
        mx1 = fmaxf(mx1, __shfl_xor_sync(0xffffffffu, mx1, 1));
        mx1 = fmaxf(mx1, __shfl_xor_sync(0xffffffffu, mx1, 2));
        float mn0 = fmaxf(m0, mx0), mn1 = fmaxf(m1, mx1);
        float cor0 = ex2f(m0 - mn0), cor1 = ex2f(m1 - mn1);
        m0 = mn0; m1 = mn1;

        float rs0 = 0.f, rs1 = 0.f;
#pragma unroll
        for (int nk = 0; nk < 8; nk++) {
            s[nk][0] = ex2f(s[nk][0] - mn0);
            s[nk][1] = ex2f(s[nk][1] - mn0);
            s[nk][2] = ex2f(s[nk][2] - mn1);
            s[nk][3] = ex2f(s[nk][3] - mn1);
            rs0 += s[nk][0] + s[nk][1];
            rs1 += s[nk][2] + s[nk][3];
        }
        rs0 += __shfl_xor_sync(0xffffffffu, rs0, 1);
        rs0 += __shfl_xor_sync(0xffffffffu, rs0, 2);
        rs1 += __shfl_xor_sync(0xffffffffu, rs1, 1);
        rs1 += __shfl_xor_sync(0xffffffffu, rs1, 2);
        l0 = l0 * cor0 + rs0;
        l1 = l1 * cor1 + rs1;

#pragma unroll
        for (int nf = 0; nf < 16; nf++) {
            o[nf][0] *= cor0; o[nf][1] *= cor0;
            o[nf][2] *= cor1; o[nf][3] *= cor1;
        }

        // ---- P A-frags: fp16x2 packs of S C-frags (no transpose needed) ----
        uint32_t aP[4][4];
#pragma unroll
        for (int kf = 0; kf < 4; kf++) {
            aP[kf][0] = pack_f16x2(s[2 * kf][0],     s[2 * kf][1]);
            aP[kf][1] = pack_f16x2(s[2 * kf][2],     s[2 * kf][3]);
            aP[kf][2] = pack_f16x2(s[2 * kf + 1][0], s[2 * kf + 1][1]);
            aP[kf][3] = pack_f16x2(s[2 * kf + 1][2], s[2 * kf + 1][3]);
        }

        // ---- O += P V : ldmatrix B-frags from d-major Vt tile ----
#pragma unroll
        for (int kf = 0; kf < 4; kf++) {
#pragma unroll
            for (int dp = 0; dp < 8; dp++) {
                int row = dp * 16 + b_row;   // d row 0..127
                uint32_t addr = vbase + (uint32_t)row * 128
                              + (((kf * 2 + b_hi) ^ (row & 7)) << 4);
                uint32_t bf[4];
                ldsm_x4(bf, addr);
                mma_f16(o[2 * dp],     aP[kf], bf[0], bf[1]);
                mma_f16(o[2 * dp + 1], aP[kf], bf[2], bf[3]);
            }
        }

        slot++; if (slot >= 3) slot = 0;
    }

    // ---- write output: fp16 [b*n, h*a] ----
    const float il0 = 1.f / l0, il1 = 1.f / l1;
    const int b2 = bh >> 4, h2 = bh & 15;
    __half* o0 = O + (size_t)(b2 * N + row0) * HD + h2 * A;
    __half* o1 = O + (size_t)(b2 * N + row1) * HD + h2 * A;
#pragma unroll
    for (int nf = 0; nf < 16; nf++) {
        int col = nf * 8 + 2 * tig;
        *(uint32_t*)(o0 + col) = pack_f16x2(o[nf][0] * il0, o[nf][1] * il0);
        *(uint32_t*)(o1 + col) = pack_f16x2(o[nf][2] * il1, o[nf][3] * il1);
    }
}

// ---------------------------------------------------------------------------
extern "C" void kernel_launch(void* const* d_in, const int* in_sizes, int n_in,
                              void* d_out, int out_size) {
    const float* q  = (const float*)d_in[0];
    const float* Wq = (const float*)d_in[1];
    const float* Wk = (const float*)d_in[2];
    const float* Wv = (const float*)d_in[3];
    const float* Wo = (const float*)d_in[4];
    float* out = (float*)d_out;

    __half *qh, *Wqh, *Wkh, *Wvh, *Woh, *Qh, *Kh, *VTh, *AOh;
    cudaGetSymbolAddress((void**)&qh,  g_qh);
    cudaGetSymbolAddress((void**)&Wqh, g_Wqh);
    cudaGetSymbolAddress((void**)&Wkh, g_Wkh);
    cudaGetSymbolAddress((void**)&Wvh, g_Wvh);
    cudaGetSymbolAddress((void**)&Woh, g_Woh);
    cudaGetSymbolAddress((void**)&Qh,  g_Qh);
    cudaGetSymbolAddress((void**)&Kh,  g_Kh);
    cudaGetSymbolAddress((void**)&VTh, g_VTh);
    cudaGetSymbolAddress((void**)&AOh, g_AOh);

    cudaFuncSetAttribute(qkv_gemm, cudaFuncAttributeMaxDynamicSharedMemorySize,
                         GEMM_SMEM);
    cudaFuncSetAttribute(out_gemm, cudaFuncAttributeMaxDynamicSharedMemorySize,
                         GEMM_SMEM);
    cudaFuncSetAttribute(attn_mma_kernel,
                         cudaFuncAttributeMaxDynamicSharedMemorySize, ATTN_SMEM);

    // rope sin/cos table + fp16 conversion pre-pass (q + 4 weights)
    rope_table_kernel<<<(N * 64) / 256, 256>>>();
    {
        int total = NQ4 + 4 * NW4;   // 6,291,456
        cvt_all_kernel<<<total / 256, 256>>>(
            (const float4*)q, (const float4*)Wq, (const float4*)Wk,
            (const float4*)Wv, (const float4*)Wo,
            qh, Wqh, Wkh, Wvh, Woh);
    }

    // fused QKV projections (rope + scale fused; V stored transposed)
    qkv_gemm<<<dim3(16, 32, 3), 256, GEMM_SMEM>>>(qh, Wqh, Wkh, Wvh, Qh, Kh, VTh);

    // fp16 tensor-core causal flash attention (64q CTAs, 64-key tiles)
    attn_mma_kernel<<<dim3(N / AQT, B * H), 128, ATTN_SMEM>>>(Qh, Kh, VTh, AOh);

    // output projection (fp32 result)
    out_gemm<<<dim3(16, 32), 256, GEMM_SMEM>>>(AOh, Woh, out);
}